// round 4
// baseline (speedup 1.0000x reference)
#include <cuda_runtime.h>
#include <math.h>
#include <stdint.h>

// Problem constants
#define Bc 4
#define Nc 8192
#define Ec 128
#define Hc 4
#define Dc 32
#define PADc 16
#define Wc 33
#define BHc 16
#define Mc (Bc * Nc)   // 32768 rows

// Scratch (device globals: no allocation allowed in kernel_launch)
__device__ float g_Q[(size_t)BHc * Nc * Dc];     // (B,H,N,D)
__device__ float g_K[(size_t)BHc * Nc * Dc];
__device__ float g_V[(size_t)BHc * Nc * Dc];
__device__ float g_ctx[(size_t)Mc * Ec];          // (B,N,E)

__device__ __forceinline__ uint32_t f2tf32(float x) {
    uint32_t r;
    asm("cvt.rna.tf32.f32 %0, %1;" : "=r"(r) : "f"(x));
    return r;
}

__device__ __forceinline__ uint32_t hi_bits(float x) {
    return __float_as_uint(x) & 0xFFFFE000u;
}

__device__ __forceinline__ void mma_tf32(
    float& c0, float& c1, float& c2, float& c3,
    uint32_t a0, uint32_t a1, uint32_t a2, uint32_t a3,
    uint32_t b0, uint32_t b1)
{
    asm volatile(
        "mma.sync.aligned.m16n8k8.row.col.f32.tf32.tf32.f32 "
        "{%0,%1,%2,%3}, {%4,%5,%6,%7}, {%8,%9}, {%0,%1,%2,%3};\n"
        : "+f"(c0), "+f"(c1), "+f"(c2), "+f"(c3)
        : "r"(a0), "r"(a1), "r"(a2), "r"(a3), "r"(b0), "r"(b1));
}

// ---- cp.async helpers (8-byte granularity) --------------------------------
__device__ __forceinline__ void cp8(float* dst, const float* src) {
    uint32_t d = (uint32_t)__cvta_generic_to_shared(dst);
    asm volatile("cp.async.ca.shared.global [%0], [%1], 8;\n" :: "r"(d), "l"(src) : "memory");
}
__device__ __forceinline__ void cpcommit() {
    asm volatile("cp.async.commit_group;\n" ::: "memory");
}
__device__ __forceinline__ void cpwait1() {
    asm volatile("cp.async.wait_group 1;\n" ::: "memory");
}
__device__ __forceinline__ void cpwait0() {
    asm volatile("cp.async.wait_group 0;\n" ::: "memory");
}

#define PSTR 36   // smem row stride (floats): 36 mod 32 = 4 -> conflict-free frags

// Stage one 128x32 chunk of A and B (raw fp32) via cp.async
__device__ __forceinline__ void stage_chunk(
    float* bufA, float* bufB,
    const float* __restrict__ A, const float* __restrict__ B,
    int m0, int k0, int tid)
{
#pragma unroll
    for (int o = 0; o < 8; o++) {
        int li  = tid + o * 256;        // 0..2047
        int r   = li >> 4;              // 0..127
        int c2  = (li & 15) * 2;        // 0,2,..,30
        cp8(bufA + r * PSTR + c2, A + (size_t)(m0 + r) * 128 + k0 + c2);
        cp8(bufB + r * PSTR + c2, B + (size_t)r * 128 + k0 + c2);
    }
}

// ---------------------------------------------------------------------------
// tf32 MMA GEMM core: C(128x128) = A(128x128) @ B(128x128)^T  (+bias)
// 256 threads = 8 warps; warp grid 4(M) x 2(N); warp tile 32x64.
// cp.async double-buffered over 4 K-chunks; cvt to tf32 at fragment load.
// ---------------------------------------------------------------------------
#define GEMM_PIPE_BODY(A_PTR, B_PTR, EPILOGUE)                                  \
    extern __shared__ float smp[];                                              \
    const int tid  = threadIdx.x;                                               \
    const int wid  = tid >> 5;                                                  \
    const int lane = tid & 31;                                                  \
    const int wm   = wid >> 1;                                                  \
    const int wn   = wid & 1;                                                   \
    const int gr   = lane >> 2;                                                 \
    const int gc   = lane & 3;                                                  \
    const int m0   = blockIdx.x * 128;                                          \
    float* bufA[2] = { smp,            smp + 2 * 128 * PSTR };                  \
    float* bufB[2] = { smp + 128 * PSTR, smp + 3 * 128 * PSTR };                \
    float acc[2][8][4];                                                         \
    _Pragma("unroll")                                                           \
    for (int i = 0; i < 2; i++)                                                 \
        _Pragma("unroll")                                                       \
        for (int j = 0; j < 8; j++)                                             \
            _Pragma("unroll")                                                   \
            for (int e = 0; e < 4; e++) acc[i][j][e] = 0.f;                     \
    stage_chunk(bufA[0], bufB[0], A_PTR, B_PTR, m0, 0, tid);                    \
    cpcommit();                                                                 \
    _Pragma("unroll")                                                           \
    for (int it = 0; it < 4; it++) {                                            \
        if (it < 3) {                                                           \
            stage_chunk(bufA[(it + 1) & 1], bufB[(it + 1) & 1],                 \
                        A_PTR, B_PTR, m0, (it + 1) * 32, tid);                  \
            cpcommit();                                                         \
            cpwait1();                                                          \
        } else {                                                                \
            cpwait0();                                                          \
        }                                                                       \
        __syncthreads();                                                        \
        const float* Ac = bufA[it & 1];                                         \
        const float* Bq = bufB[it & 1];                                         \
        _Pragma("unroll")                                                       \
        for (int kk = 0; kk < 32; kk += 8) {                                    \
            uint32_t af[2][4];                                                  \
            _Pragma("unroll")                                                   \
            for (int i = 0; i < 2; i++) {                                       \
                int rb = (wm * 32 + i * 16 + gr) * PSTR + kk + gc;              \
                af[i][0] = f2tf32(Ac[rb]);                                      \
                af[i][1] = f2tf32(Ac[rb + 8 * PSTR]);                           \
                af[i][2] = f2tf32(Ac[rb + 4]);                                  \
                af[i][3] = f2tf32(Ac[rb + 8 * PSTR + 4]);                       \
            }                                                                   \
            uint32_t bf[8][2];                                                  \
            _Pragma("unroll")                                                   \
            for (int j = 0; j < 8; j++) {                                       \
                int nb = (wn * 64 + j * 8 + gr) * PSTR + kk + gc;               \
                bf[j][0] = f2tf32(Bq[nb]);                                      \
                bf[j][1] = f2tf32(Bq[nb + 4]);                                  \
            }                                                                   \
            _Pragma("unroll")                                                   \
            for (int i = 0; i < 2; i++)                                         \
                _Pragma("unroll")                                               \
                for (int j = 0; j < 8; j++)                                     \
                    mma_tf32(acc[i][j][0], acc[i][j][1], acc[i][j][2], acc[i][j][3], \
                             af[i][0], af[i][1], af[i][2], af[i][3],            \
                             bf[j][0], bf[j][1]);                               \
        }                                                                       \
        __syncthreads();                                                        \
    }                                                                           \
    EPILOGUE

// ---------------------------------------------------------------------------
// Kernel 1: fused QKV projection -> (B,H,N,D) scatter.  grid = (256, 3)
// ---------------------------------------------------------------------------
__global__ __launch_bounds__(256, 2) void qkv_mma(
    const float* __restrict__ q,
    const float* __restrict__ Wq, const float* __restrict__ bq,
    const float* __restrict__ Wk, const float* __restrict__ bk,
    const float* __restrict__ Wv, const float* __restrict__ bv)
{
    const int which = blockIdx.y;
    const float* __restrict__ Wm = (which == 0) ? Wq : ((which == 1) ? Wk : Wv);
    const float* __restrict__ bm = (which == 0) ? bq : ((which == 1) ? bk : bv);
    float* __restrict__ outp = (which == 0) ? g_Q : ((which == 1) ? g_K : g_V);

    GEMM_PIPE_BODY(q, Wm,
    {
        _Pragma("unroll")
        for (int i = 0; i < 2; i++) {
            _Pragma("unroll")
            for (int e2 = 0; e2 < 2; e2++) {
                int m = m0 + wm * 32 + i * 16 + gr + e2 * 8;
                int b = m >> 13;
                int n = m & 8191;
                _Pragma("unroll")
                for (int j = 0; j < 8; j++) {
                    int col = wn * 64 + j * 8 + gc * 2;
                    int h = col >> 5;
                    int d = col & 31;
                    float2 v;
                    v.x = acc[i][j][e2 * 2 + 0] + bm[col];
                    v.y = acc[i][j][e2 * 2 + 1] + bm[col + 1];
                    *(float2*)(outp + ((size_t)(b * Hc + h) * Nc + n) * Dc + d) = v;
                }
            }
        }
    })
}

// ---------------------------------------------------------------------------
// Kernel 3: output projection. out = ctx @ Wo.T + bo -> d_out (B,N,E)
// ---------------------------------------------------------------------------
__global__ __launch_bounds__(256, 2) void out_mma(
    const float* __restrict__ Wo, const float* __restrict__ bo,
    float* __restrict__ outp)
{
    const float* __restrict__ ctxp = g_ctx;
    GEMM_PIPE_BODY(ctxp, Wo,
    {
        _Pragma("unroll")
        for (int i = 0; i < 2; i++) {
            _Pragma("unroll")
            for (int e2 = 0; e2 < 2; e2++) {
                int m = m0 + wm * 32 + i * 16 + gr + e2 * 8;
                _Pragma("unroll")
                for (int j = 0; j < 8; j++) {
                    int col = wn * 64 + j * 8 + gc * 2;
                    float2 v;
                    v.x = acc[i][j][e2 * 2 + 0] + bo[col];
                    v.y = acc[i][j][e2 * 2 + 1] + bo[col + 1];
                    *(float2*)(outp + (size_t)m * 128 + col) = v;
                }
            }
        }
    })
}

// ---------------------------------------------------------------------------
// Kernel 2: warp-independent tensorized sliding-window attention.
// Block = 128 queries (4 warps x 32 queries); each warp owns a dense
// 64-key window [q0-16, q0+48) of its 32-query band. After one staging
// __syncthreads, warps are fully independent (per-warp S scratch).
// S = Q@Kwin^T via split-tf32 (exact scores); OOB keys are zero-padded
// (score exactly 0, matching reference); out-of-band entries zeroed.
// grid = (N/128, BH), 128 threads.
// ---------------------------------------------------------------------------
#define QS 36     // Qs/Ks stride
#define VS 165    // Vt stride: 165 mod 32 = 5 -> conflict-free stores & loads
#define SS 68     // per-warp S stride: 68 mod 32 = 4

__global__ __launch_bounds__(128) void attn_mma(float* __restrict__ probs_out)
{
    extern __shared__ float sm[];
    float* Qs   = sm;                       // 128 x 36 raw fp32
    float* Ks   = Qs + 128 * QS;            // 160 x 36 raw fp32 (zero OOB)
    float* Vt   = Ks + 160 * QS;            // 32 x 165 tf32 transposed (zero OOB)
    float* Sall = Vt + 32 * VS;             // 4 warps x (32 x 68)

    const int tile = blockIdx.x;            // 0..63
    const int bh   = blockIdx.y;            // 0..15
    const int tid  = threadIdx.x;
    const int wid  = tid >> 5;              // 0..3
    const int lane = tid & 31;
    const int gr   = lane >> 2;
    const int gc   = lane & 3;
    const int n0   = tile * 128;
    const int g0   = n0 - PADc;

    const float* __restrict__ Qg = g_Q + (size_t)bh * Nc * Dc;
    const float* __restrict__ Kg = g_K + (size_t)bh * Nc * Dc;
    const float* __restrict__ Vg = g_V + (size_t)bh * Nc * Dc;

    // Stage Q (128x32)
#pragma unroll
    for (int l = 0; l < 8; l++) {
        int idx = tid + l * 128;            // 0..1023
        int r   = idx >> 3;
        int c4  = (idx & 7) * 4;
        *(float4*)&Qs[r * QS + c4] = *(const float4*)(Qg + (size_t)(n0 + r) * 32 + c4);
    }
    // Stage K (160x32 raw, zero OOB) and V transposed (tf32, zero OOB)
#pragma unroll
    for (int l = 0; l < 10; l++) {
        int idx = tid + l * 128;            // 0..1279
        int r   = idx >> 3;                 // 0..159
        int c4  = (idx & 7) * 4;
        int grow = g0 + r;
        float4 kv = make_float4(0.f, 0.f, 0.f, 0.f);
        float4 vv = make_float4(0.f, 0.f, 0.f, 0.f);
        if (grow >= 0 && grow < Nc) {
            kv = *(const float4*)(Kg + (size_t)grow * 32 + c4);
            vv = *(const float4*)(Vg + (size_t)grow * 32 + c4);
        }
        *(float4*)&Ks[r * QS + c4] = kv;
        Vt[(c4 + 0) * VS + r] = __uint_as_float(f2tf32(vv.x));
        Vt[(c4 + 1) * VS + r] = __uint_as_float(f2tf32(vv.y));
        Vt[(c4 + 2) * VS + r] = __uint_as_float(f2tf32(vv.z));
        Vt[(c4 + 3) * VS + r] = __uint_as_float(f2tf32(vv.w));
    }
    __syncthreads();

    float* Sw = Sall + wid * (32 * SS);
    const int woff = wid * 32;              // warp's key-window offset in staged rows

    // ---- QK^T: S(32x64) via split-tf32 (hh + hl + lh) ----
    float acc[2][8][4];
#pragma unroll
    for (int i = 0; i < 2; i++)
#pragma unroll
        for (int j = 0; j < 8; j++)
#pragma unroll
            for (int e = 0; e < 4; e++) acc[i][j][e] = 0.f;

#pragma unroll
    for (int kk = 0; kk < 32; kk += 8) {
        uint32_t ah[2][4], al[2][4];
#pragma unroll
        for (int i = 0; i < 2; i++) {
            int rb = (woff + i * 16 + gr) * QS + kk + gc;
            float x0 = Qs[rb];
            float x1 = Qs[rb + 8 * QS];
            float x2 = Qs[rb + 4];
            float x3 = Qs[rb + 8 * QS + 4];
            ah[i][0] = hi_bits(x0); al[i][0] = __float_as_uint(x0 - __uint_as_float(ah[i][0]));
            ah[i][1] = hi_bits(x1); al[i][1] = __float_as_uint(x1 - __uint_as_float(ah[i][1]));
            ah[i][2] = hi_bits(x2); al[i][2] = __float_as_uint(x2 - __uint_as_float(ah[i][2]));
            ah[i][3] = hi_bits(x3); al[i][3] = __float_as_uint(x3 - __uint_as_float(ah[i][3]));
        }
        uint32_t bhf[8][2], blf[8][2];
#pragma unroll
        for (int j = 0; j < 8; j++) {
            int nb = (woff + j * 8 + gr) * QS + kk + gc;
            float y0 = Ks[nb];
            float y1 = Ks[nb + 4];
            bhf[j][0] = hi_bits(y0); blf[j][0] = __float_as_uint(y0 - __uint_as_float(bhf[j][0]));
            bhf[j][1] = hi_bits(y1); blf[j][1] = __float_as_uint(y1 - __uint_as_float(bhf[j][1]));
        }
#pragma unroll
        for (int i = 0; i < 2; i++)
#pragma unroll
            for (int j = 0; j < 8; j++) {
                mma_tf32(acc[i][j][0], acc[i][j][1], acc[i][j][2], acc[i][j][3],
                         al[i][0], al[i][1], al[i][2], al[i][3], bhf[j][0], bhf[j][1]);
                mma_tf32(acc[i][j][0], acc[i][j][1], acc[i][j][2], acc[i][j][3],
                         ah[i][0], ah[i][1], ah[i][2], ah[i][3], blf[j][0], blf[j][1]);
                mma_tf32(acc[i][j][0], acc[i][j][1], acc[i][j][2], acc[i][j][3],
                         ah[i][0], ah[i][1], ah[i][2], ah[i][3], bhf[j][0], bhf[j][1]);
            }
    }

    // Epilogue: scale in-band (0 <= c-m <= 32), zero out-of-band
    const float scale = 0.17677669529663687f;   // 1/sqrt(32)
#pragma unroll
    for (int i = 0; i < 2; i++) {
#pragma unroll
        for (int j = 0; j < 8; j++) {
            int c0 = j * 8 + gc * 2;
#pragma unroll
            for (int e2 = 0; e2 < 2; e2++) {
                int m = i * 16 + gr + e2 * 8;
                int w0 = c0 - m;
                float v0 = (w0 >= 0     && w0 <= 32) ? acc[i][j][e2 * 2 + 0] * scale : 0.f;
                float v1 = (w0 + 1 >= 0 && w0 + 1 <= 32) ? acc[i][j][e2 * 2 + 1] * scale : 0.f;
                float2 v; v.x = v0; v.y = v1;
                *(float2*)&Sw[m * SS + c0] = v;
            }
        }
    }
    __syncwarp();

    // ---- softmax per query (lane = local query m) ----
    {
        const int m = lane;
        float* row = Sw + m * SS;
        float sc[33];
#pragma unroll
        for (int w = 0; w < 33; w++) sc[w] = row[m + w];
        float mx = sc[0];
#pragma unroll
        for (int w = 1; w < 33; w++) mx = fmaxf(mx, sc[w]);
        float ssum = 0.f;
#pragma unroll
        for (int w = 0; w < 33; w++) { sc[w] = __expf(sc[w] - mx); ssum += sc[w]; }
        const float rinv = 1.f / ssum;
        float* __restrict__ pr = probs_out + ((size_t)bh * Nc + n0 + wid * 32 + m) * Wc;
#pragma unroll
        for (int w = 0; w < 33; w++) {
            float p = sc[w] * rinv;
            pr[w] = p;
            row[m + w] = __uint_as_float(f2tf32(p));
        }
    }
    __syncwarp();

    // ---- ctx = P(32x64) @ V(64x32) via tf32 MMA ----
    float acc2[2][4][4];
#pragma unroll
    for (int i = 0; i < 2; i++)
#pragma unroll
        for (int j = 0; j < 4; j++)
#pragma unroll
            for (int e = 0; e < 4; e++) acc2[i][j][e] = 0.f;

#pragma unroll
    for (int kk = 0; kk < 64; kk += 8) {
        uint32_t af[2][4];
#pragma unroll
        for (int i = 0; i < 2; i++) {
            int rb = (i * 16 + gr) * SS + kk + gc;
            af[i][0] = __float_as_uint(Sw[rb]);
            af[i][1] = __float_as_uint(Sw[rb + 8 * SS]);
            af[i][2] = __float_as_uint(Sw[rb + 4]);
            af[i][3] = __float_as_uint(Sw[rb + 8 * SS + 4]);
        }
        uint32_t bf[4][2];
#pragma unroll
        for (int j = 0; j < 4; j++) {
            int nb = (j * 8 + gr) * VS + woff + kk + gc;
            bf[j][0] = __float_as_uint(Vt[nb]);
            bf[j][1] = __float_as_uint(Vt[nb + 4]);
        }
#pragma unroll
        for (int i = 0; i < 2; i++)
#pragma unroll
            for (int j = 0; j < 4; j++)
                mma_tf32(acc2[i][j][0], acc2[i][j][1], acc2[i][j][2], acc2[i][j][3],
                         af[i][0], af[i][1], af[i][2], af[i][3], bf[j][0], bf[j][1]);
    }

    // Epilogue: ctx -> (B,N,E)
    const int b = bh >> 2;
    const int h = bh & 3;
#pragma unroll
    for (int i = 0; i < 2; i++) {
#pragma unroll
        for (int j = 0; j < 4; j++) {
            int d = j * 8 + gc * 2;
#pragma unroll
            for (int e2 = 0; e2 < 2; e2++) {
                int m = i * 16 + gr + e2 * 8;
                float2 v;
                v.x = acc2[i][j][e2 * 2 + 0];
                v.y = acc2[i][j][e2 * 2 + 1];
                *(float2*)(g_ctx + ((size_t)(b * Nc) + n0 + wid * 32 + m) * Ec + h * 32 + d) = v;
            }
        }
    }
}

// ---------------------------------------------------------------------------
extern "C" void kernel_launch(void* const* d_in, const int* in_sizes, int n_in,
                              void* d_out, int out_size)
{
    (void)in_sizes; (void)n_in; (void)out_size;
    const float* q  = (const float*)d_in[0];
    const float* Wq = (const float*)d_in[1];
    const float* bq = (const float*)d_in[2];
    const float* Wk = (const float*)d_in[3];
    const float* bk = (const float*)d_in[4];
    const float* Wv = (const float*)d_in[5];
    const float* bv = (const float*)d_in[6];
    const float* Wo = (const float*)d_in[7];
    const float* bo = (const float*)d_in[8];

    float* outp  = (float*)d_out;                         // (B,N,E)
    float* probs = outp + (size_t)Bc * Nc * Ec;           // (B,H,N,W)

    const int gemm_smem = 4 * 128 * PSTR * 4;             // 73728 B
    const int attn_smem = (128 * QS + 160 * QS + 32 * VS + 4 * 32 * SS) * 4; // 97408 B
    cudaFuncSetAttribute(qkv_mma,  cudaFuncAttributeMaxDynamicSharedMemorySize, gemm_smem);
    cudaFuncSetAttribute(out_mma,  cudaFuncAttributeMaxDynamicSharedMemorySize, gemm_smem);
    cudaFuncSetAttribute(attn_mma, cudaFuncAttributeMaxDynamicSharedMemorySize, attn_smem);

    qkv_mma<<<dim3(Mc / 128, 3), 256, gemm_smem>>>(q, Wq, bq, Wk, bk, Wv, bv);
    attn_mma<<<dim3(Nc / 128, BHc), 128, attn_smem>>>(probs);
    out_mma<<<dim3(Mc / 128, 1), 256, gemm_smem>>>(Wo, bo, outp);
}

// round 5
// speedup vs baseline: 1.0004x; 1.0004x over previous
#include <cuda_runtime.h>
#include <math.h>
#include <stdint.h>

// Problem constants
#define Bc 4
#define Nc 8192
#define Ec 128
#define Hc 4
#define Dc 32
#define PADc 16
#define Wc 33
#define BHc 16
#define Mc (Bc * Nc)   // 32768 rows

// Scratch (device globals: no allocation allowed in kernel_launch)
__device__ float g_Q[(size_t)BHc * Nc * Dc];     // (B,H,N,D)
__device__ float g_K[(size_t)BHc * Nc * Dc];
__device__ float g_V[(size_t)BHc * Nc * Dc];
__device__ float g_ctx[(size_t)Mc * Ec];          // (B,N,E)

__device__ __forceinline__ uint32_t f2tf32(float x) {
    uint32_t r;
    asm("cvt.rna.tf32.f32 %0, %1;" : "=r"(r) : "f"(x));
    return r;
}

__device__ __forceinline__ uint32_t hi_bits(float x) {
    return __float_as_uint(x) & 0xFFFFE000u;
}

__device__ __forceinline__ void mma_tf32(
    float& c0, float& c1, float& c2, float& c3,
    uint32_t a0, uint32_t a1, uint32_t a2, uint32_t a3,
    uint32_t b0, uint32_t b1)
{
    asm volatile(
        "mma.sync.aligned.m16n8k8.row.col.f32.tf32.tf32.f32 "
        "{%0,%1,%2,%3}, {%4,%5,%6,%7}, {%8,%9}, {%0,%1,%2,%3};\n"
        : "+f"(c0), "+f"(c1), "+f"(c2), "+f"(c3)
        : "r"(a0), "r"(a1), "r"(a2), "r"(a3), "r"(b0), "r"(b1));
}

// Fragment-major smem indices for one 128x32 K-chunk:
//  A: 4 kk-blocks x 8 m16-blocks x 32 lanes x 4 values  -> LDS.128 per frag
//  B: 4 kk-blocks x 16 n8-blocks x 32 lanes x 2 values  -> LDS.64  per frag
#define AFI(kk,m16,lane,idx) ((((kk)*8 + (m16))*32 + (lane))*4 + (idx))
#define BFI(kk,n8,lane,idx)  ((((kk)*16 + (n8))*32 + (lane))*2 + (idx))

// ---------------------------------------------------------------------------
// tf32 MMA GEMM core: C(128x128) = A(128x128) @ B(128x128)^T  (+bias)
// 256 threads = 8 warps; warp grid 4(M) x 2(N); warp tile 32x64.
// Staging converts fp32 -> tf32 and scatters into fragment-major layout.
// ---------------------------------------------------------------------------
#define GEMM_FRAG_BODY(A_PTR, B_PTR, EPILOGUE)                                  \
    __shared__ uint32_t Af[4096];                                               \
    __shared__ uint32_t Bf[4096];                                               \
    const int tid  = threadIdx.x;                                               \
    const int wid  = tid >> 5;                                                  \
    const int lane = tid & 31;                                                  \
    const int wm   = wid >> 1;                                                  \
    const int wn   = wid & 1;                                                   \
    const int gr   = lane >> 2;                                                 \
    const int gc   = lane & 3;                                                  \
    const int m0   = blockIdx.x * 128;                                          \
    (void)gr; (void)gc;                                                         \
    float acc[2][8][4];                                                         \
    _Pragma("unroll")                                                           \
    for (int i = 0; i < 2; i++)                                                 \
        _Pragma("unroll")                                                       \
        for (int j = 0; j < 8; j++)                                             \
            _Pragma("unroll")                                                   \
            for (int e = 0; e < 4; e++) acc[i][j][e] = 0.f;                     \
    for (int k0 = 0; k0 < 128; k0 += 32) {                                      \
        _Pragma("unroll")                                                       \
        for (int l = 0; l < 4; l++) {                                           \
            int li  = tid + l * 256;       /* 0..1023 */                        \
            int r   = li >> 3;             /* 0..127  */                        \
            int c4  = (li & 7) * 4;        /* 0,4,..,28 */                      \
            int kk  = c4 >> 3;                                                  \
            float4 va = *(const float4*)(A_PTR + (size_t)(m0 + r) * 128 + k0 + c4); \
            int m16   = r >> 4;                                                 \
            int lane0 = (r & 7) * 4;                                            \
            int idxA  = ((r >> 3) & 1) + ((c4 >> 2) & 1) * 2;                   \
            uint32_t* pa = &Af[AFI(kk, m16, lane0, idxA)];                      \
            pa[0]  = f2tf32(va.x);                                              \
            pa[4]  = f2tf32(va.y);                                              \
            pa[8]  = f2tf32(va.z);                                              \
            pa[12] = f2tf32(va.w);                                              \
            float4 vb = *(const float4*)(B_PTR + (size_t)r * 128 + k0 + c4);    \
            int n8   = r >> 3;                                                  \
            int idxB = (c4 >> 2) & 1;                                           \
            uint32_t* pb = &Bf[BFI(kk, n8, lane0, idxB)];                       \
            pb[0] = f2tf32(vb.x);                                               \
            pb[2] = f2tf32(vb.y);                                               \
            pb[4] = f2tf32(vb.z);                                               \
            pb[6] = f2tf32(vb.w);                                               \
        }                                                                       \
        __syncthreads();                                                        \
        _Pragma("unroll")                                                       \
        for (int kk = 0; kk < 4; kk++) {                                        \
            uint32_t af[2][4];                                                  \
            _Pragma("unroll")                                                   \
            for (int i = 0; i < 2; i++)                                         \
                *(uint4*)af[i] = *(const uint4*)&Af[AFI(kk, wm * 2 + i, lane, 0)]; \
            uint32_t bf[8][2];                                                  \
            _Pragma("unroll")                                                   \
            for (int j = 0; j < 8; j++)                                         \
                *(uint2*)bf[j] = *(const uint2*)&Bf[BFI(kk, wn * 8 + j, lane, 0)]; \
            _Pragma("unroll")                                                   \
            for (int i = 0; i < 2; i++)                                         \
                _Pragma("unroll")                                               \
                for (int j = 0; j < 8; j++)                                     \
                    mma_tf32(acc[i][j][0], acc[i][j][1], acc[i][j][2], acc[i][j][3], \
                             af[i][0], af[i][1], af[i][2], af[i][3],            \
                             bf[j][0], bf[j][1]);                               \
        }                                                                       \
        __syncthreads();                                                        \
    }                                                                           \
    EPILOGUE

// ---------------------------------------------------------------------------
// Kernel 1: fused QKV projection -> (B,H,N,D) scatter.  grid = (256, 3)
// ---------------------------------------------------------------------------
__global__ __launch_bounds__(256, 2) void qkv_mma(
    const float* __restrict__ q,
    const float* __restrict__ Wq, const float* __restrict__ bq,
    const float* __restrict__ Wk, const float* __restrict__ bk,
    const float* __restrict__ Wv, const float* __restrict__ bv)
{
    const int which = blockIdx.y;
    const float* __restrict__ Wm = (which == 0) ? Wq : ((which == 1) ? Wk : Wv);
    const float* __restrict__ bm = (which == 0) ? bq : ((which == 1) ? bk : bv);
    float* __restrict__ outp = (which == 0) ? g_Q : ((which == 1) ? g_K : g_V);

    GEMM_FRAG_BODY(q, Wm,
    {
        _Pragma("unroll")
        for (int i = 0; i < 2; i++) {
            _Pragma("unroll")
            for (int e2 = 0; e2 < 2; e2++) {
                int m = m0 + wm * 32 + i * 16 + gr + e2 * 8;
                int b = m >> 13;
                int n = m & 8191;
                _Pragma("unroll")
                for (int j = 0; j < 8; j++) {
                    int col = wn * 64 + j * 8 + gc * 2;
                    int h = col >> 5;
                    int d = col & 31;
                    float2 v;
                    v.x = acc[i][j][e2 * 2 + 0] + bm[col];
                    v.y = acc[i][j][e2 * 2 + 1] + bm[col + 1];
                    *(float2*)(outp + ((size_t)(b * Hc + h) * Nc + n) * Dc + d) = v;
                }
            }
        }
    })
}

// ---------------------------------------------------------------------------
// Kernel 3: output projection. out = ctx @ Wo.T + bo -> d_out (B,N,E)
// ---------------------------------------------------------------------------
__global__ __launch_bounds__(256, 2) void out_mma(
    const float* __restrict__ Wo, const float* __restrict__ bo,
    float* __restrict__ outp)
{
    const float* __restrict__ ctxp = g_ctx;
    GEMM_FRAG_BODY(ctxp, Wo,
    {
        _Pragma("unroll")
        for (int i = 0; i < 2; i++) {
            _Pragma("unroll")
            for (int e2 = 0; e2 < 2; e2++) {
                int m = m0 + wm * 32 + i * 16 + gr + e2 * 8;
                _Pragma("unroll")
                for (int j = 0; j < 8; j++) {
                    int col = wn * 64 + j * 8 + gc * 2;
                    float2 v;
                    v.x = acc[i][j][e2 * 2 + 0] + bo[col];
                    v.y = acc[i][j][e2 * 2 + 1] + bo[col + 1];
                    *(float2*)(outp + (size_t)m * 128 + col) = v;
                }
            }
        }
    })
}

// ---------------------------------------------------------------------------
// Kernel 2: warp-independent tensorized sliding-window attention.
// Block = 128 queries (4 warps x 32 queries); each warp owns a dense
// 64-key window of its 32-query band. S = Q@Kwin^T via split-tf32
// (exact scores); OOB keys zero-padded (score exactly 0, matching
// reference); out-of-band entries zeroed. Probs staged compactly in
// smem (reusing the warp's dead Qs region) then stored warp-coalesced.
// grid = (N/128, BH), 128 threads.
// ---------------------------------------------------------------------------
#define QS 36     // Qs/Ks stride
#define VS 165    // Vt stride: 165 mod 32 = 5 -> conflict-free stores & loads
#define SS 68     // per-warp S stride: 68 mod 32 = 4

__global__ __launch_bounds__(128) void attn_mma(float* __restrict__ probs_out)
{
    extern __shared__ float sm[];
    float* Qs   = sm;                       // 128 x 36 raw fp32 (reused for probs)
    float* Ks   = Qs + 128 * QS;            // 160 x 36 raw fp32 (zero OOB)
    float* Vt   = Ks + 160 * QS;            // 32 x 165 tf32 transposed (zero OOB)
    float* Sall = Vt + 32 * VS;             // 4 warps x (32 x 68)

    const int tile = blockIdx.x;            // 0..63
    const int bh   = blockIdx.y;            // 0..15
    const int tid  = threadIdx.x;
    const int wid  = tid >> 5;              // 0..3
    const int lane = tid & 31;
    const int gr   = lane >> 2;
    const int gc   = lane & 3;
    const int n0   = tile * 128;
    const int g0   = n0 - PADc;

    const float* __restrict__ Qg = g_Q + (size_t)bh * Nc * Dc;
    const float* __restrict__ Kg = g_K + (size_t)bh * Nc * Dc;
    const float* __restrict__ Vg = g_V + (size_t)bh * Nc * Dc;

    // Stage Q (128x32)
#pragma unroll
    for (int l = 0; l < 8; l++) {
        int idx = tid + l * 128;            // 0..1023
        int r   = idx >> 3;
        int c4  = (idx & 7) * 4;
        *(float4*)&Qs[r * QS + c4] = *(const float4*)(Qg + (size_t)(n0 + r) * 32 + c4);
    }
    // Stage K (160x32 raw, zero OOB) and V transposed (tf32, zero OOB)
#pragma unroll
    for (int l = 0; l < 10; l++) {
        int idx = tid + l * 128;            // 0..1279
        int r   = idx >> 3;                 // 0..159
        int c4  = (idx & 7) * 4;
        int grow = g0 + r;
        float4 kv = make_float4(0.f, 0.f, 0.f, 0.f);
        float4 vv = make_float4(0.f, 0.f, 0.f, 0.f);
        if (grow >= 0 && grow < Nc) {
            kv = *(const float4*)(Kg + (size_t)grow * 32 + c4);
            vv = *(const float4*)(Vg + (size_t)grow * 32 + c4);
        }
        *(float4*)&Ks[r * QS + c4] = kv;
        Vt[(c4 + 0) * VS + r] = __uint_as_float(f2tf32(vv.x));
        Vt[(c4 + 1) * VS + r] = __uint_as_float(f2tf32(vv.y));
        Vt[(c4 + 2) * VS + r] = __uint_as_float(f2tf32(vv.z));
        Vt[(c4 + 3) * VS + r] = __uint_as_float(f2tf32(vv.w));
    }
    __syncthreads();

    float* Sw = Sall + wid * (32 * SS);
    const int woff = wid * 32;              // warp's key-window offset in staged rows

    // ---- QK^T: S(32x64) via split-tf32 (hh + hl + lh) ----
    float acc[2][8][4];
#pragma unroll
    for (int i = 0; i < 2; i++)
#pragma unroll
        for (int j = 0; j < 8; j++)
#pragma unroll
            for (int e = 0; e < 4; e++) acc[i][j][e] = 0.f;

#pragma unroll
    for (int kk = 0; kk < 32; kk += 8) {
        uint32_t ah[2][4], al[2][4];
#pragma unroll
        for (int i = 0; i < 2; i++) {
            int rb = (woff + i * 16 + gr) * QS + kk + gc;
            float x0 = Qs[rb];
            float x1 = Qs[rb + 8 * QS];
            float x2 = Qs[rb + 4];
            float x3 = Qs[rb + 8 * QS + 4];
            ah[i][0] = hi_bits(x0); al[i][0] = __float_as_uint(x0 - __uint_as_float(ah[i][0]));
            ah[i][1] = hi_bits(x1); al[i][1] = __float_as_uint(x1 - __uint_as_float(ah[i][1]));
            ah[i][2] = hi_bits(x2); al[i][2] = __float_as_uint(x2 - __uint_as_float(ah[i][2]));
            ah[i][3] = hi_bits(x3); al[i][3] = __float_as_uint(x3 - __uint_as_float(ah[i][3]));
        }
        uint32_t bhf[8][2], blf[8][2];
#pragma unroll
        for (int j = 0; j < 8; j++) {
            int nb = (woff + j * 8 + gr) * QS + kk + gc;
            float y0 = Ks[nb];
            float y1 = Ks[nb + 4];
            bhf[j][0] = hi_bits(y0); blf[j][0] = __float_as_uint(y0 - __uint_as_float(bhf[j][0]));
            bhf[j][1] = hi_bits(y1); blf[j][1] = __float_as_uint(y1 - __uint_as_float(bhf[j][1]));
        }
#pragma unroll
        for (int i = 0; i < 2; i++)
#pragma unroll
            for (int j = 0; j < 8; j++) {
                mma_tf32(acc[i][j][0], acc[i][j][1], acc[i][j][2], acc[i][j][3],
                         al[i][0], al[i][1], al[i][2], al[i][3], bhf[j][0], bhf[j][1]);
                mma_tf32(acc[i][j][0], acc[i][j][1], acc[i][j][2], acc[i][j][3],
                         ah[i][0], ah[i][1], ah[i][2], ah[i][3], blf[j][0], blf[j][1]);
                mma_tf32(acc[i][j][0], acc[i][j][1], acc[i][j][2], acc[i][j][3],
                         ah[i][0], ah[i][1], ah[i][2], ah[i][3], bhf[j][0], bhf[j][1]);
            }
    }

    // Epilogue: scale in-band (0 <= c-m <= 32), zero out-of-band
    const float scale = 0.17677669529663687f;   // 1/sqrt(32)
#pragma unroll
    for (int i = 0; i < 2; i++) {
#pragma unroll
        for (int j = 0; j < 8; j++) {
            int c0 = j * 8 + gc * 2;
#pragma unroll
            for (int e2 = 0; e2 < 2; e2++) {
                int m = i * 16 + gr + e2 * 8;
                int w0 = c0 - m;
                float v0 = (w0 >= 0     && w0 <= 32) ? acc[i][j][e2 * 2 + 0] * scale : 0.f;
                float v1 = (w0 + 1 >= 0 && w0 + 1 <= 32) ? acc[i][j][e2 * 2 + 1] * scale : 0.f;
                float2 v; v.x = v0; v.y = v1;
                *(float2*)&Sw[m * SS + c0] = v;
            }
        }
    }
    __syncwarp();

    // ---- softmax per query (lane = local query m) ----
    // Probs staged compactly into the warp's own (dead) Qs region:
    // stride 33 == 1 mod 32 -> conflict-free scatter.
    float* Pc = Qs + wid * 32 * QS;          // 32*36 floats available >= 32*33
    {
        const int m = lane;
        float* row = Sw + m * SS;
        float sc[33];
#pragma unroll
        for (int w = 0; w < 33; w++) sc[w] = row[m + w];
        float mx = sc[0];
#pragma unroll
        for (int w = 1; w < 33; w++) mx = fmaxf(mx, sc[w]);
        float ssum = 0.f;
#pragma unroll
        for (int w = 0; w < 33; w++) { sc[w] = __expf(sc[w] - mx); ssum += sc[w]; }
        const float rinv = 1.f / ssum;
#pragma unroll
        for (int w = 0; w < 33; w++) {
            float p = sc[w] * rinv;
            Pc[m * 33 + w] = p;
            row[m + w] = __uint_as_float(f2tf32(p));
        }
    }
    __syncwarp();

    // Warp-coalesced probs store: 32 queries x 33 floats contiguous in gmem.
    {
        float* gp = probs_out + ((size_t)bh * Nc + n0 + wid * 32) * Wc;
        const float4* Ps4 = (const float4*)Pc;
        float4* Gp4 = (float4*)gp;
#pragma unroll
        for (int i = lane; i < 264; i += 32)   // 1056 floats = 264 float4
            Gp4[i] = Ps4[i];
    }

    // ---- ctx = P(32x64) @ V(64x32) via tf32 MMA ----
    float acc2[2][4][4];
#pragma unroll
    for (int i = 0; i < 2; i++)
#pragma unroll
        for (int j = 0; j < 4; j++)
#pragma unroll
            for (int e = 0; e < 4; e++) acc2[i][j][e] = 0.f;

#pragma unroll
    for (int kk = 0; kk < 64; kk += 8) {
        uint32_t af[2][4];
#pragma unroll
        for (int i = 0; i < 2; i++) {
            int rb = (i * 16 + gr) * SS + kk + gc;
            af[i][0] = __float_as_uint(Sw[rb]);
            af[i][1] = __float_as_uint(Sw[rb + 8 * SS]);
            af[i][2] = __float_as_uint(Sw[rb + 4]);
            af[i][3] = __float_as_uint(Sw[rb + 8 * SS + 4]);
        }
        uint32_t bf[4][2];
#pragma unroll
        for (int j = 0; j < 4; j++) {
            int nb = (j * 8 + gr) * VS + woff + kk + gc;
            bf[j][0] = __float_as_uint(Vt[nb]);
            bf[j][1] = __float_as_uint(Vt[nb + 4]);
        }
#pragma unroll
        for (int i = 0; i < 2; i++)
#pragma unroll
            for (int j = 0; j < 4; j++)
                mma_tf32(acc2[i][j][0], acc2[i][j][1], acc2[i][j][2], acc2[i][j][3],
                         af[i][0], af[i][1], af[i][2], af[i][3], bf[j][0], bf[j][1]);
    }

    // Epilogue: ctx -> (B,N,E)
    const int b = bh >> 2;
    const int h = bh & 3;
#pragma unroll
    for (int i = 0; i < 2; i++) {
#pragma unroll
        for (int j = 0; j < 4; j++) {
            int d = j * 8 + gc * 2;
#pragma unroll
            for (int e2 = 0; e2 < 2; e2++) {
                int m = i * 16 + gr + e2 * 8;
                float2 v;
                v.x = acc2[i][j][e2 * 2 + 0];
                v.y = acc2[i][j][e2 * 2 + 1];
                *(float2*)(g_ctx + ((size_t)(b * Nc) + n0 + wid * 32 + m) * Ec + h * 32 + d) = v;
            }
        }
    }
}

// ---------------------------------------------------------------------------
extern "C" void kernel_launch(void* const* d_in, const int* in_sizes, int n_in,
                              void* d_out, int out_size)
{
    (void)in_sizes; (void)n_in; (void)out_size;
    const float* q  = (const float*)d_in[0];
    const float* Wq = (const float*)d_in[1];
    const float* bq = (const float*)d_in[2];
    const float* Wk = (const float*)d_in[3];
    const float* bk = (const float*)d_in[4];
    const float* Wv = (const float*)d_in[5];
    const float* bv = (const float*)d_in[6];
    const float* Wo = (const float*)d_in[7];
    const float* bo = (const float*)d_in[8];

    float* outp  = (float*)d_out;                         // (B,N,E)
    float* probs = outp + (size_t)Bc * Nc * Ec;           // (B,H,N,W)

    const int attn_smem = (128 * QS + 160 * QS + 32 * VS + 4 * 32 * SS) * 4; // 97408 B
    cudaFuncSetAttribute(attn_mma, cudaFuncAttributeMaxDynamicSharedMemorySize, attn_smem);

    qkv_mma<<<dim3(Mc / 128, 3), 256>>>(q, Wq, bq, Wk, bk, Wv, bv);
    attn_mma<<<dim3(Nc / 128, BHc), 128, attn_smem>>>(probs);
    out_mma<<<dim3(Mc / 128, 1), 256>>>(Wo, bo, outp);
}

// round 6
// speedup vs baseline: 1.1055x; 1.1051x over previous
#include <cuda_runtime.h>
#include <math.h>
#include <stdint.h>

// Problem constants
#define Bc 4
#define Nc 8192
#define Ec 128
#define Hc 4
#define Dc 32
#define PADc 16
#define Wc 33
#define BHc 16
#define Mc (Bc * Nc)   // 32768 rows

// Scratch (device globals: no allocation allowed in kernel_launch)
__device__ float g_Q[(size_t)BHc * Nc * Dc];     // (B,H,N,D)
__device__ float g_K[(size_t)BHc * Nc * Dc];
__device__ float g_V[(size_t)BHc * Nc * Dc];
__device__ float g_ctx[(size_t)Mc * Ec];          // (B,N,E)

__device__ __forceinline__ uint32_t f2tf32(float x) {
    uint32_t r;
    asm("cvt.rna.tf32.f32 %0, %1;" : "=r"(r) : "f"(x));
    return r;
}

__device__ __forceinline__ uint32_t hi_bits(float x) {
    return __float_as_uint(x) & 0xFFFFE000u;
}

__device__ __forceinline__ void mma_tf32(
    float& c0, float& c1, float& c2, float& c3,
    uint32_t a0, uint32_t a1, uint32_t a2, uint32_t a3,
    uint32_t b0, uint32_t b1)
{
    asm volatile(
        "mma.sync.aligned.m16n8k8.row.col.f32.tf32.tf32.f32 "
        "{%0,%1,%2,%3}, {%4,%5,%6,%7}, {%8,%9}, {%0,%1,%2,%3};\n"
        : "+f"(c0), "+f"(c1), "+f"(c2), "+f"(c3)
        : "r"(a0), "r"(a1), "r"(a2), "r"(a3), "r"(b0), "r"(b1));
}

#define PSTR 36   // smem row stride: 36 mod 32 = 4 -> conflict-free frags & stores

// ---------------------------------------------------------------------------
// tf32 MMA GEMM core: C(128x128) = A(128x128) @ B(128x128)^T  (+bias)
// 256 threads = 8 warps; warp grid 4(M) x 2(N); warp tile 32x64.
// Staging-time cvt (proven R3 core) + register prefetch of the next K-chunk
// so LDG latency hides behind the 64 MMAs of the current chunk.
// ---------------------------------------------------------------------------
#define GEMM_PF_BODY(A_PTR, B_PTR, EPILOGUE)                                    \
    extern __shared__ float smg[];                                              \
    uint32_t* As = (uint32_t*)smg;                                              \
    uint32_t* Bs = (uint32_t*)smg + 128 * PSTR;                                 \
    const int tid  = threadIdx.x;                                               \
    const int wid  = tid >> 5;                                                  \
    const int lane = tid & 31;                                                  \
    const int wm   = wid >> 1;                                                  \
    const int wn   = wid & 1;                                                   \
    const int gr   = lane >> 2;                                                 \
    const int gc   = lane & 3;                                                  \
    const int m0   = blockIdx.x * 128;                                          \
    float4 pa[4], pb[4];                                                        \
    _Pragma("unroll")                                                           \
    for (int l = 0; l < 4; l++) {                                               \
        int li = tid + l * 256; int r = li >> 3; int c4 = (li & 7) * 4;         \
        pa[l] = *(const float4*)(A_PTR + (size_t)(m0 + r) * 128 + c4);          \
        pb[l] = *(const float4*)(B_PTR + (size_t)r * 128 + c4);                 \
    }                                                                           \
    float acc[2][8][4];                                                         \
    _Pragma("unroll")                                                           \
    for (int i = 0; i < 2; i++)                                                 \
        _Pragma("unroll")                                                       \
        for (int j = 0; j < 8; j++)                                             \
            _Pragma("unroll")                                                   \
            for (int e = 0; e < 4; e++) acc[i][j][e] = 0.f;                     \
    _Pragma("unroll")                                                           \
    for (int it = 0; it < 4; it++) {                                            \
        _Pragma("unroll")                                                       \
        for (int l = 0; l < 4; l++) {                                           \
            int li = tid + l * 256; int r = li >> 3; int c4 = (li & 7) * 4;     \
            uint4 ua;                                                           \
            ua.x = f2tf32(pa[l].x); ua.y = f2tf32(pa[l].y);                     \
            ua.z = f2tf32(pa[l].z); ua.w = f2tf32(pa[l].w);                     \
            *(uint4*)&As[r * PSTR + c4] = ua;                                   \
            uint4 ub;                                                           \
            ub.x = f2tf32(pb[l].x); ub.y = f2tf32(pb[l].y);                     \
            ub.z = f2tf32(pb[l].z); ub.w = f2tf32(pb[l].w);                     \
            *(uint4*)&Bs[r * PSTR + c4] = ub;                                   \
        }                                                                       \
        __syncthreads();                                                        \
        if (it < 3) {                                                           \
            _Pragma("unroll")                                                   \
            for (int l = 0; l < 4; l++) {                                       \
                int li = tid + l * 256; int r = li >> 3; int c4 = (li & 7) * 4; \
                pa[l] = *(const float4*)(A_PTR + (size_t)(m0 + r) * 128 + (it + 1) * 32 + c4); \
                pb[l] = *(const float4*)(B_PTR + (size_t)r * 128 + (it + 1) * 32 + c4); \
            }                                                                   \
        }                                                                       \
        _Pragma("unroll")                                                       \
        for (int kk = 0; kk < 32; kk += 8) {                                    \
            uint32_t af[2][4];                                                  \
            _Pragma("unroll")                                                   \
            for (int i = 0; i < 2; i++) {                                       \
                int rb = (wm * 32 + i * 16 + gr) * PSTR + kk + gc;              \
                af[i][0] = As[rb];                                              \
                af[i][1] = As[rb + 8 * PSTR];                                   \
                af[i][2] = As[rb + 4];                                          \
                af[i][3] = As[rb + 8 * PSTR + 4];                               \
            }                                                                   \
            uint32_t bf[8][2];                                                  \
            _Pragma("unroll")                                                   \
            for (int j = 0; j < 8; j++) {                                       \
                int nb = (wn * 64 + j * 8 + gr) * PSTR + kk + gc;               \
                bf[j][0] = Bs[nb];                                              \
                bf[j][1] = Bs[nb + 4];                                          \
            }                                                                   \
            _Pragma("unroll")                                                   \
            for (int i = 0; i < 2; i++)                                         \
                _Pragma("unroll")                                               \
                for (int j = 0; j < 8; j++)                                     \
                    mma_tf32(acc[i][j][0], acc[i][j][1], acc[i][j][2], acc[i][j][3], \
                             af[i][0], af[i][1], af[i][2], af[i][3],            \
                             bf[j][0], bf[j][1]);                               \
        }                                                                       \
        __syncthreads();                                                        \
    }                                                                           \
    EPILOGUE

// ---------------------------------------------------------------------------
// Kernel 1: fused QKV projection -> (B,H,N,D) scatter.  grid = (256, 3)
// ---------------------------------------------------------------------------
__global__ __launch_bounds__(256, 2) void qkv_mma(
    const float* __restrict__ q,
    const float* __restrict__ Wq, const float* __restrict__ bq,
    const float* __restrict__ Wk, const float* __restrict__ bk,
    const float* __restrict__ Wv, const float* __restrict__ bv)
{
    const int which = blockIdx.y;
    const float* __restrict__ Wm = (which == 0) ? Wq : ((which == 1) ? Wk : Wv);
    const float* __restrict__ bm = (which == 0) ? bq : ((which == 1) ? bk : bv);
    float* __restrict__ outp = (which == 0) ? g_Q : ((which == 1) ? g_K : g_V);

    GEMM_PF_BODY(q, Wm,
    {
        _Pragma("unroll")
        for (int i = 0; i < 2; i++) {
            _Pragma("unroll")
            for (int e2 = 0; e2 < 2; e2++) {
                int m = m0 + wm * 32 + i * 16 + gr + e2 * 8;
                int b = m >> 13;
                int n = m & 8191;
                _Pragma("unroll")
                for (int j = 0; j < 8; j++) {
                    int col = wn * 64 + j * 8 + gc * 2;
                    int h = col >> 5;
                    int d = col & 31;
                    float2 v;
                    v.x = acc[i][j][e2 * 2 + 0] + bm[col];
                    v.y = acc[i][j][e2 * 2 + 1] + bm[col + 1];
                    *(float2*)(outp + ((size_t)(b * Hc + h) * Nc + n) * Dc + d) = v;
                }
            }
        }
    })
}

// ---------------------------------------------------------------------------
// Kernel 3: output projection. out = ctx @ Wo.T + bo -> d_out (B,N,E)
// ---------------------------------------------------------------------------
__global__ __launch_bounds__(256, 2) void out_mma(
    const float* __restrict__ Wo, const float* __restrict__ bo,
    float* __restrict__ outp)
{
    const float* __restrict__ ctxp = g_ctx;
    GEMM_PF_BODY(ctxp, Wo,
    {
        _Pragma("unroll")
        for (int i = 0; i < 2; i++) {
            _Pragma("unroll")
            for (int e2 = 0; e2 < 2; e2++) {
                int m = m0 + wm * 32 + i * 16 + gr + e2 * 8;
                _Pragma("unroll")
                for (int j = 0; j < 8; j++) {
                    int col = wn * 64 + j * 8 + gc * 2;
                    float2 v;
                    v.x = acc[i][j][e2 * 2 + 0] + bo[col];
                    v.y = acc[i][j][e2 * 2 + 1] + bo[col + 1];
                    *(float2*)(outp + (size_t)m * 128 + col) = v;
                }
            }
        }
    })
}

// ---------------------------------------------------------------------------
// Kernel 2: warp-independent tensorized sliding-window attention.
// Block = 128 queries (4 warps x 32 queries); each warp owns a dense
// 64-key window of its 32-query band. S = Q@Kwin^T via split-tf32 (exact
// scores); OOB keys zero-padded (score exactly 0, matching reference);
// out-of-band entries zeroed. MMAs covering provably-zero band regions
// are skipped (25% of QK and PV tensor work). Probs staged compactly in
// smem (dead Qs region) then stored warp-coalesced.
// grid = (N/128, BH), 128 threads.
// ---------------------------------------------------------------------------
#define QS 36     // Qs/Ks stride
#define VS 165    // Vt stride: 165 mod 32 = 5 -> conflict-free stores & loads
#define SS 68     // per-warp S stride: 68 mod 32 = 4

__global__ __launch_bounds__(128) void attn_mma(float* __restrict__ probs_out)
{
    extern __shared__ float sm[];
    float* Qs   = sm;                       // 128 x 36 raw fp32 (reused for probs)
    float* Ks   = Qs + 128 * QS;            // 160 x 36 raw fp32 (zero OOB)
    float* Vt   = Ks + 160 * QS;            // 32 x 165 tf32 transposed (zero OOB)
    float* Sall = Vt + 32 * VS;             // 4 warps x (32 x 68)

    const int tile = blockIdx.x;            // 0..63
    const int bh   = blockIdx.y;            // 0..15
    const int tid  = threadIdx.x;
    const int wid  = tid >> 5;              // 0..3
    const int lane = tid & 31;
    const int gr   = lane >> 2;
    const int gc   = lane & 3;
    const int n0   = tile * 128;
    const int g0   = n0 - PADc;

    const float* __restrict__ Qg = g_Q + (size_t)bh * Nc * Dc;
    const float* __restrict__ Kg = g_K + (size_t)bh * Nc * Dc;
    const float* __restrict__ Vg = g_V + (size_t)bh * Nc * Dc;

    // Stage Q (128x32)
#pragma unroll
    for (int l = 0; l < 8; l++) {
        int idx = tid + l * 128;            // 0..1023
        int r   = idx >> 3;
        int c4  = (idx & 7) * 4;
        *(float4*)&Qs[r * QS + c4] = *(const float4*)(Qg + (size_t)(n0 + r) * 32 + c4);
    }
    // Stage K (160x32 raw, zero OOB) and V transposed (tf32, zero OOB)
#pragma unroll
    for (int l = 0; l < 10; l++) {
        int idx = tid + l * 128;            // 0..1279
        int r   = idx >> 3;                 // 0..159
        int c4  = (idx & 7) * 4;
        int grow = g0 + r;
        float4 kv = make_float4(0.f, 0.f, 0.f, 0.f);
        float4 vv = make_float4(0.f, 0.f, 0.f, 0.f);
        if (grow >= 0 && grow < Nc) {
            kv = *(const float4*)(Kg + (size_t)grow * 32 + c4);
            vv = *(const float4*)(Vg + (size_t)grow * 32 + c4);
        }
        *(float4*)&Ks[r * QS + c4] = kv;
        Vt[(c4 + 0) * VS + r] = __uint_as_float(f2tf32(vv.x));
        Vt[(c4 + 1) * VS + r] = __uint_as_float(f2tf32(vv.y));
        Vt[(c4 + 2) * VS + r] = __uint_as_float(f2tf32(vv.z));
        Vt[(c4 + 3) * VS + r] = __uint_as_float(f2tf32(vv.w));
    }
    __syncthreads();

    float* Sw = Sall + wid * (32 * SS);
    const int woff = wid * 32;              // warp's key-window offset in staged rows

    // ---- QK^T: S(32x64) via split-tf32 (hh + hl + lh) ----
    // Band: row m uses cols [m, m+32]. Fragment block (i,j) touches rows
    // [i*16, i*16+16) x cols [j*8, j*8+8) -> needed iff j*8+7 >= i*16 and
    // j*8 <= i*16+47.  i=0: j in [0,5];  i=1: j in [2,7].
    float acc[2][8][4];
#pragma unroll
    for (int i = 0; i < 2; i++)
#pragma unroll
        for (int j = 0; j < 8; j++)
#pragma unroll
            for (int e = 0; e < 4; e++) acc[i][j][e] = 0.f;

#pragma unroll
    for (int kk = 0; kk < 32; kk += 8) {
        uint32_t ah[2][4], al[2][4];
#pragma unroll
        for (int i = 0; i < 2; i++) {
            int rb = (woff + i * 16 + gr) * QS + kk + gc;
            float x0 = Qs[rb];
            float x1 = Qs[rb + 8 * QS];
            float x2 = Qs[rb + 4];
            float x3 = Qs[rb + 8 * QS + 4];
            ah[i][0] = hi_bits(x0); al[i][0] = __float_as_uint(x0 - __uint_as_float(ah[i][0]));
            ah[i][1] = hi_bits(x1); al[i][1] = __float_as_uint(x1 - __uint_as_float(ah[i][1]));
            ah[i][2] = hi_bits(x2); al[i][2] = __float_as_uint(x2 - __uint_as_float(ah[i][2]));
            ah[i][3] = hi_bits(x3); al[i][3] = __float_as_uint(x3 - __uint_as_float(ah[i][3]));
        }
        uint32_t bhf[8][2], blf[8][2];
#pragma unroll
        for (int j = 0; j < 8; j++) {
            int nb = (woff + j * 8 + gr) * QS + kk + gc;
            float y0 = Ks[nb];
            float y1 = Ks[nb + 4];
            bhf[j][0] = hi_bits(y0); blf[j][0] = __float_as_uint(y0 - __uint_as_float(bhf[j][0]));
            bhf[j][1] = hi_bits(y1); blf[j][1] = __float_as_uint(y1 - __uint_as_float(bhf[j][1]));
        }
#pragma unroll
        for (int i = 0; i < 2; i++)
#pragma unroll
            for (int j = 0; j < 8; j++) {
                if (i == 0 && j >= 6) continue;   // fully out-of-band
                if (i == 1 && j <= 1) continue;   // fully out-of-band
                mma_tf32(acc[i][j][0], acc[i][j][1], acc[i][j][2], acc[i][j][3],
                         al[i][0], al[i][1], al[i][2], al[i][3], bhf[j][0], bhf[j][1]);
                mma_tf32(acc[i][j][0], acc[i][j][1], acc[i][j][2], acc[i][j][3],
                         ah[i][0], ah[i][1], ah[i][2], ah[i][3], blf[j][0], blf[j][1]);
                mma_tf32(acc[i][j][0], acc[i][j][1], acc[i][j][2], acc[i][j][3],
                         ah[i][0], ah[i][1], ah[i][2], ah[i][3], bhf[j][0], bhf[j][1]);
            }
    }

    // Epilogue: scale in-band (0 <= c-m <= 32), zero out-of-band
    const float scale = 0.17677669529663687f;   // 1/sqrt(32)
#pragma unroll
    for (int i = 0; i < 2; i++) {
#pragma unroll
        for (int j = 0; j < 8; j++) {
            int c0 = j * 8 + gc * 2;
#pragma unroll
            for (int e2 = 0; e2 < 2; e2++) {
                int m = i * 16 + gr + e2 * 8;
                int w0 = c0 - m;
                float v0 = (w0 >= 0     && w0 <= 32) ? acc[i][j][e2 * 2 + 0] * scale : 0.f;
                float v1 = (w0 + 1 >= 0 && w0 + 1 <= 32) ? acc[i][j][e2 * 2 + 1] * scale : 0.f;
                float2 v; v.x = v0; v.y = v1;
                *(float2*)&Sw[m * SS + c0] = v;
            }
        }
    }
    __syncwarp();

    // ---- softmax per query (lane = local query m) ----
    // Probs staged compactly into the warp's own (dead) Qs region:
    // stride 33 == 1 mod 32 -> conflict-free scatter.
    float* Pc = Qs + wid * 32 * QS;          // 32*36 floats available >= 32*33
    {
        const int m = lane;
        float* row = Sw + m * SS;
        float sc[33];
#pragma unroll
        for (int w = 0; w < 33; w++) sc[w] = row[m + w];
        float mx = sc[0];
#pragma unroll
        for (int w = 1; w < 33; w++) mx = fmaxf(mx, sc[w]);
        float ssum = 0.f;
#pragma unroll
        for (int w = 0; w < 33; w++) { sc[w] = __expf(sc[w] - mx); ssum += sc[w]; }
        const float rinv = 1.f / ssum;
#pragma unroll
        for (int w = 0; w < 33; w++) {
            float p = sc[w] * rinv;
            Pc[m * 33 + w] = p;
            row[m + w] = __uint_as_float(f2tf32(p));
        }
    }
    __syncwarp();

    // Warp-coalesced probs store: 32 queries x 33 floats contiguous in gmem.
    {
        float* gp = probs_out + ((size_t)bh * Nc + n0 + wid * 32) * Wc;
        const float4* Ps4 = (const float4*)Pc;
        float4* Gp4 = (float4*)gp;
#pragma unroll
        for (int i = lane; i < 264; i += 32)   // 1056 floats = 264 float4
            Gp4[i] = Ps4[i];
    }

    // ---- ctx = P(32x64) @ V(64x32) via tf32 MMA ----
    // Row block i uses P cols [i*16, i*16+47] -> i=0: kk8 in [0,5]; i=1: [2,7].
    float acc2[2][4][4];
#pragma unroll
    for (int i = 0; i < 2; i++)
#pragma unroll
        for (int j = 0; j < 4; j++)
#pragma unroll
            for (int e = 0; e < 4; e++) acc2[i][j][e] = 0.f;

#pragma unroll
    for (int kk8 = 0; kk8 < 8; kk8++) {
        const int kk = kk8 * 8;
        uint32_t bf[4][2];
#pragma unroll
        for (int j = 0; j < 4; j++) {
            int nb = (j * 8 + gr) * VS + woff + kk + gc;
            bf[j][0] = __float_as_uint(Vt[nb]);
            bf[j][1] = __float_as_uint(Vt[nb + 4]);
        }
#pragma unroll
        for (int i = 0; i < 2; i++) {
            if (i == 0 && kk8 >= 6) continue;   // P cols 48+ are zero for rows 0..15
            if (i == 1 && kk8 <= 1) continue;   // P cols <16 are zero for rows 16..31
            uint32_t af[4];
            int rb = (i * 16 + gr) * SS + kk + gc;
            af[0] = __float_as_uint(Sw[rb]);
            af[1] = __float_as_uint(Sw[rb + 8 * SS]);
            af[2] = __float_as_uint(Sw[rb + 4]);
            af[3] = __float_as_uint(Sw[rb + 8 * SS + 4]);
#pragma unroll
            for (int j = 0; j < 4; j++)
                mma_tf32(acc2[i][j][0], acc2[i][j][1], acc2[i][j][2], acc2[i][j][3],
                         af[0], af[1], af[2], af[3], bf[j][0], bf[j][1]);
        }
    }

    // Epilogue: ctx -> (B,N,E)
    const int b = bh >> 2;
    const int h = bh & 3;
#pragma unroll
    for (int i = 0; i < 2; i++) {
#pragma unroll
        for (int j = 0; j < 4; j++) {
            int d = j * 8 + gc * 2;
#pragma unroll
            for (int e2 = 0; e2 < 2; e2++) {
                int m = i * 16 + gr + e2 * 8;
                float2 v;
                v.x = acc2[i][j][e2 * 2 + 0];
                v.y = acc2[i][j][e2 * 2 + 1];
                *(float2*)(g_ctx + ((size_t)(b * Nc) + n0 + wid * 32 + m) * Ec + h * 32 + d) = v;
            }
        }
    }
}

// ---------------------------------------------------------------------------
extern "C" void kernel_launch(void* const* d_in, const int* in_sizes, int n_in,
                              void* d_out, int out_size)
{
    (void)in_sizes; (void)n_in; (void)out_size;
    const float* q  = (const float*)d_in[0];
    const float* Wq = (const float*)d_in[1];
    const float* bq = (const float*)d_in[2];
    const float* Wk = (const float*)d_in[3];
    const float* bk = (const float*)d_in[4];
    const float* Wv = (const float*)d_in[5];
    const float* bv = (const float*)d_in[6];
    const float* Wo = (const float*)d_in[7];
    const float* bo = (const float*)d_in[8];

    float* outp  = (float*)d_out;                         // (B,N,E)
    float* probs = outp + (size_t)Bc * Nc * Ec;           // (B,H,N,W)

    const int gemm_smem = 2 * 128 * PSTR * 4;             // 36864 B (< 48K default)
    const int attn_smem = (128 * QS + 160 * QS + 32 * VS + 4 * 32 * SS) * 4; // 97408 B
    cudaFuncSetAttribute(attn_mma, cudaFuncAttributeMaxDynamicSharedMemorySize, attn_smem);

    qkv_mma<<<dim3(Mc / 128, 3), 256, gemm_smem>>>(q, Wq, bq, Wk, bk, Wv, bv);
    attn_mma<<<dim3(Nc / 128, BHc), 128, attn_smem>>>(probs);
    out_mma<<<dim3(Mc / 128, 1), 256, gemm_smem>>>(Wo, bo, outp);
}

// round 7
// speedup vs baseline: 1.2261x; 1.1091x over previous
#include <cuda_runtime.h>
#include <math.h>
#include <stdint.h>

// Problem constants
#define Bc 4
#define Nc 8192
#define Ec 128
#define Hc 4
#define Dc 32
#define PADc 16
#define Wc 33
#define BHc 16
#define Mc (Bc * Nc)   // 32768 rows

// Scratch (device globals: no allocation allowed in kernel_launch)
__device__ float g_Q[(size_t)BHc * Nc * Dc];     // (B,H,N,D)
__device__ float g_K[(size_t)BHc * Nc * Dc];
__device__ float g_V[(size_t)BHc * Nc * Dc];
__device__ float g_ctx[(size_t)Mc * Ec];          // (B,N,E)

__device__ __forceinline__ uint32_t f2tf32(float x) {
    uint32_t r;
    asm("cvt.rna.tf32.f32 %0, %1;" : "=r"(r) : "f"(x));
    return r;
}

__device__ __forceinline__ uint32_t hi_bits(float x) {
    return __float_as_uint(x) & 0xFFFFE000u;
}

__device__ __forceinline__ void mma_tf32(
    float& c0, float& c1, float& c2, float& c3,
    uint32_t a0, uint32_t a1, uint32_t a2, uint32_t a3,
    uint32_t b0, uint32_t b1)
{
    asm volatile(
        "mma.sync.aligned.m16n8k8.row.col.f32.tf32.tf32.f32 "
        "{%0,%1,%2,%3}, {%4,%5,%6,%7}, {%8,%9}, {%0,%1,%2,%3};\n"
        : "+f"(c0), "+f"(c1), "+f"(c2), "+f"(c3)
        : "r"(a0), "r"(a1), "r"(a2), "r"(a3), "r"(b0), "r"(b1));
}

// ---------------------------------------------------------------------------
// tf32 MMA GEMM core (R3 core — best measured variant):
// C(128x128) = A(128x128) @ B(128x128)^T  (+bias)
// 256 threads = 8 warps; warp grid 4(M) x 2(N); warp tile 32x64.
// smem stride 36 => fragment LDS pattern (4*(lane>>2)+(lane&3)) is
// conflict-free across all 32 banks. cvt to tf32 at staging time.
// ---------------------------------------------------------------------------
#define GEMM_MMA_BODY(A_PTR, B_PTR, EPILOGUE)                                   \
    __shared__ uint32_t As[128 * 36];                                           \
    __shared__ uint32_t Bs[128 * 36];                                           \
    const int tid  = threadIdx.x;                                               \
    const int wid  = tid >> 5;                                                  \
    const int lane = tid & 31;                                                  \
    const int wm   = wid >> 1;       /* 0..3 */                                 \
    const int wn   = wid & 1;        /* 0..1 */                                 \
    const int gr   = lane >> 2;      /* 0..7 */                                 \
    const int gc   = lane & 3;       /* 0..3 */                                 \
    const int m0   = blockIdx.x * 128;                                          \
    float acc[2][8][4];                                                         \
    _Pragma("unroll")                                                           \
    for (int i = 0; i < 2; i++)                                                 \
        _Pragma("unroll")                                                       \
        for (int j = 0; j < 8; j++)                                             \
            _Pragma("unroll")                                                   \
            for (int e = 0; e < 4; e++) acc[i][j][e] = 0.f;                     \
    for (int k0 = 0; k0 < 128; k0 += 32) {                                      \
        _Pragma("unroll")                                                       \
        for (int l = 0; l < 4; l++) {                                           \
            int li = tid + l * 256;                                             \
            int r  = li >> 3;                                                   \
            int c4 = (li & 7) * 4;                                              \
            float4 va = *(const float4*)(A_PTR + (size_t)(m0 + r) * 128 + k0 + c4); \
            As[r * 36 + c4 + 0] = f2tf32(va.x);                                 \
            As[r * 36 + c4 + 1] = f2tf32(va.y);                                 \
            As[r * 36 + c4 + 2] = f2tf32(va.z);                                 \
            As[r * 36 + c4 + 3] = f2tf32(va.w);                                 \
            float4 vb = *(const float4*)(B_PTR + (size_t)r * 128 + k0 + c4);    \
            Bs[r * 36 + c4 + 0] = f2tf32(vb.x);                                 \
            Bs[r * 36 + c4 + 1] = f2tf32(vb.y);                                 \
            Bs[r * 36 + c4 + 2] = f2tf32(vb.z);                                 \
            Bs[r * 36 + c4 + 3] = f2tf32(vb.w);                                 \
        }                                                                       \
        __syncthreads();                                                        \
        _Pragma("unroll")                                                       \
        for (int kk = 0; kk < 32; kk += 8) {                                    \
            uint32_t af[2][4];                                                  \
            _Pragma("unroll")                                                   \
            for (int i = 0; i < 2; i++) {                                       \
                int rbase = (wm * 32 + i * 16 + gr) * 36 + kk + gc;             \
                af[i][0] = As[rbase];                                           \
                af[i][1] = As[rbase + 8 * 36];                                  \
                af[i][2] = As[rbase + 4];                                       \
                af[i][3] = As[rbase + 8 * 36 + 4];                              \
            }                                                                   \
            uint32_t bf[8][2];                                                  \
            _Pragma("unroll")                                                   \
            for (int j = 0; j < 8; j++) {                                       \
                int nbase = (wn * 64 + j * 8 + gr) * 36 + kk + gc;              \
                bf[j][0] = Bs[nbase];                                           \
                bf[j][1] = Bs[nbase + 4];                                       \
            }                                                                   \
            _Pragma("unroll")                                                   \
            for (int i = 0; i < 2; i++)                                         \
                _Pragma("unroll")                                               \
                for (int j = 0; j < 8; j++)                                     \
                    mma_tf32(acc[i][j][0], acc[i][j][1], acc[i][j][2], acc[i][j][3], \
                             af[i][0], af[i][1], af[i][2], af[i][3],            \
                             bf[j][0], bf[j][1]);                               \
        }                                                                       \
        __syncthreads();                                                        \
    }                                                                           \
    EPILOGUE

// ---------------------------------------------------------------------------
// Kernel 1: fused QKV projection -> (B,H,N,D) scatter.  grid = (256, 3)
// ---------------------------------------------------------------------------
__global__ __launch_bounds__(256, 2) void qkv_mma(
    const float* __restrict__ q,
    const float* __restrict__ Wq, const float* __restrict__ bq,
    const float* __restrict__ Wk, const float* __restrict__ bk,
    const float* __restrict__ Wv, const float* __restrict__ bv)
{
    const int which = blockIdx.y;
    const float* __restrict__ Wm = (which == 0) ? Wq : ((which == 1) ? Wk : Wv);
    const float* __restrict__ bm = (which == 0) ? bq : ((which == 1) ? bk : bv);
    float* __restrict__ outp = (which == 0) ? g_Q : ((which == 1) ? g_K : g_V);

    GEMM_MMA_BODY(q, Wm,
    {
        _Pragma("unroll")
        for (int i = 0; i < 2; i++) {
            _Pragma("unroll")
            for (int e2 = 0; e2 < 2; e2++) {
                int m = m0 + wm * 32 + i * 16 + gr + e2 * 8;
                int b = m >> 13;
                int n = m & 8191;
                _Pragma("unroll")
                for (int j = 0; j < 8; j++) {
                    int col = wn * 64 + j * 8 + gc * 2;
                    int h = col >> 5;
                    int d = col & 31;
                    float2 v;
                    v.x = acc[i][j][e2 * 2 + 0] + bm[col];
                    v.y = acc[i][j][e2 * 2 + 1] + bm[col + 1];
                    *(float2*)(outp + ((size_t)(b * Hc + h) * Nc + n) * Dc + d) = v;
                }
            }
        }
    })
}

// ---------------------------------------------------------------------------
// Kernel 3: output projection. out = ctx @ Wo.T + bo -> d_out (B,N,E)
// ---------------------------------------------------------------------------
__global__ __launch_bounds__(256, 2) void out_mma(
    const float* __restrict__ Wo, const float* __restrict__ bo,
    float* __restrict__ outp)
{
    const float* __restrict__ ctxp = g_ctx;
    GEMM_MMA_BODY(ctxp, Wo,
    {
        _Pragma("unroll")
        for (int i = 0; i < 2; i++) {
            _Pragma("unroll")
            for (int e2 = 0; e2 < 2; e2++) {
                int m = m0 + wm * 32 + i * 16 + gr + e2 * 8;
                _Pragma("unroll")
                for (int j = 0; j < 8; j++) {
                    int col = wn * 64 + j * 8 + gc * 2;
                    float2 v;
                    v.x = acc[i][j][e2 * 2 + 0] + bo[col];
                    v.y = acc[i][j][e2 * 2 + 1] + bo[col + 1];
                    *(float2*)(outp + (size_t)m * 128 + col) = v;
                }
            }
        }
    })
}

// ---------------------------------------------------------------------------
// Kernel 2: warp-independent tensorized sliding-window attention (R6 — keep).
// Block = 128 queries (4 warps x 32 queries); each warp owns a dense
// 64-key window of its 32-query band. S = Q@Kwin^T via split-tf32 (exact
// scores); OOB keys zero-padded (score exactly 0, matching reference);
// out-of-band entries zeroed. MMAs covering provably-zero band regions
// are skipped (25% of QK and PV tensor work). Probs staged compactly in
// smem (dead Qs region) then stored warp-coalesced.
// grid = (N/128, BH), 128 threads.
// ---------------------------------------------------------------------------
#define QS 36     // Qs/Ks stride
#define VS 165    // Vt stride: 165 mod 32 = 5 -> conflict-free stores & loads
#define SS 68     // per-warp S stride: 68 mod 32 = 4

__global__ __launch_bounds__(128) void attn_mma(float* __restrict__ probs_out)
{
    extern __shared__ float sm[];
    float* Qs   = sm;                       // 128 x 36 raw fp32 (reused for probs)
    float* Ks   = Qs + 128 * QS;            // 160 x 36 raw fp32 (zero OOB)
    float* Vt   = Ks + 160 * QS;            // 32 x 165 tf32 transposed (zero OOB)
    float* Sall = Vt + 32 * VS;             // 4 warps x (32 x 68)

    const int tile = blockIdx.x;            // 0..63
    const int bh   = blockIdx.y;            // 0..15
    const int tid  = threadIdx.x;
    const int wid  = tid >> 5;              // 0..3
    const int lane = tid & 31;
    const int gr   = lane >> 2;
    const int gc   = lane & 3;
    const int n0   = tile * 128;
    const int g0   = n0 - PADc;

    const float* __restrict__ Qg = g_Q + (size_t)bh * Nc * Dc;
    const float* __restrict__ Kg = g_K + (size_t)bh * Nc * Dc;
    const float* __restrict__ Vg = g_V + (size_t)bh * Nc * Dc;

    // Stage Q (128x32)
#pragma unroll
    for (int l = 0; l < 8; l++) {
        int idx = tid + l * 128;            // 0..1023
        int r   = idx >> 3;
        int c4  = (idx & 7) * 4;
        *(float4*)&Qs[r * QS + c4] = *(const float4*)(Qg + (size_t)(n0 + r) * 32 + c4);
    }
    // Stage K (160x32 raw, zero OOB) and V transposed (tf32, zero OOB)
#pragma unroll
    for (int l = 0; l < 10; l++) {
        int idx = tid + l * 128;            // 0..1279
        int r   = idx >> 3;                 // 0..159
        int c4  = (idx & 7) * 4;
        int grow = g0 + r;
        float4 kv = make_float4(0.f, 0.f, 0.f, 0.f);
        float4 vv = make_float4(0.f, 0.f, 0.f, 0.f);
        if (grow >= 0 && grow < Nc) {
            kv = *(const float4*)(Kg + (size_t)grow * 32 + c4);
            vv = *(const float4*)(Vg + (size_t)grow * 32 + c4);
        }
        *(float4*)&Ks[r * QS + c4] = kv;
        Vt[(c4 + 0) * VS + r] = __uint_as_float(f2tf32(vv.x));
        Vt[(c4 + 1) * VS + r] = __uint_as_float(f2tf32(vv.y));
        Vt[(c4 + 2) * VS + r] = __uint_as_float(f2tf32(vv.z));
        Vt[(c4 + 3) * VS + r] = __uint_as_float(f2tf32(vv.w));
    }
    __syncthreads();

    float* Sw = Sall + wid * (32 * SS);
    const int woff = wid * 32;              // warp's key-window offset in staged rows

    // ---- QK^T: S(32x64) via split-tf32 (hh + hl + lh) ----
    // Band: row m uses cols [m, m+32]. Fragment block (i,j): i=0: j in [0,5];
    // i=1: j in [2,7]. Others provably zero.
    float acc[2][8][4];
#pragma unroll
    for (int i = 0; i < 2; i++)
#pragma unroll
        for (int j = 0; j < 8; j++)
#pragma unroll
            for (int e = 0; e < 4; e++) acc[i][j][e] = 0.f;

#pragma unroll
    for (int kk = 0; kk < 32; kk += 8) {
        uint32_t ah[2][4], al[2][4];
#pragma unroll
        for (int i = 0; i < 2; i++) {
            int rb = (woff + i * 16 + gr) * QS + kk + gc;
            float x0 = Qs[rb];
            float x1 = Qs[rb + 8 * QS];
            float x2 = Qs[rb + 4];
            float x3 = Qs[rb + 8 * QS + 4];
            ah[i][0] = hi_bits(x0); al[i][0] = __float_as_uint(x0 - __uint_as_float(ah[i][0]));
            ah[i][1] = hi_bits(x1); al[i][1] = __float_as_uint(x1 - __uint_as_float(ah[i][1]));
            ah[i][2] = hi_bits(x2); al[i][2] = __float_as_uint(x2 - __uint_as_float(ah[i][2]));
            ah[i][3] = hi_bits(x3); al[i][3] = __float_as_uint(x3 - __uint_as_float(ah[i][3]));
        }
        uint32_t bhf[8][2], blf[8][2];
#pragma unroll
        for (int j = 0; j < 8; j++) {
            int nb = (woff + j * 8 + gr) * QS + kk + gc;
            float y0 = Ks[nb];
            float y1 = Ks[nb + 4];
            bhf[j][0] = hi_bits(y0); blf[j][0] = __float_as_uint(y0 - __uint_as_float(bhf[j][0]));
            bhf[j][1] = hi_bits(y1); blf[j][1] = __float_as_uint(y1 - __uint_as_float(bhf[j][1]));
        }
#pragma unroll
        for (int i = 0; i < 2; i++)
#pragma unroll
            for (int j = 0; j < 8; j++) {
                if (i == 0 && j >= 6) continue;   // fully out-of-band
                if (i == 1 && j <= 1) continue;   // fully out-of-band
                mma_tf32(acc[i][j][0], acc[i][j][1], acc[i][j][2], acc[i][j][3],
                         al[i][0], al[i][1], al[i][2], al[i][3], bhf[j][0], bhf[j][1]);
                mma_tf32(acc[i][j][0], acc[i][j][1], acc[i][j][2], acc[i][j][3],
                         ah[i][0], ah[i][1], ah[i][2], ah[i][3], blf[j][0], blf[j][1]);
                mma_tf32(acc[i][j][0], acc[i][j][1], acc[i][j][2], acc[i][j][3],
                         ah[i][0], ah[i][1], ah[i][2], ah[i][3], bhf[j][0], bhf[j][1]);
            }
    }

    // Epilogue: scale in-band (0 <= c-m <= 32), zero out-of-band
    const float scale = 0.17677669529663687f;   // 1/sqrt(32)
#pragma unroll
    for (int i = 0; i < 2; i++) {
#pragma unroll
        for (int j = 0; j < 8; j++) {
            int c0 = j * 8 + gc * 2;
#pragma unroll
            for (int e2 = 0; e2 < 2; e2++) {
                int m = i * 16 + gr + e2 * 8;
                int w0 = c0 - m;
                float v0 = (w0 >= 0     && w0 <= 32) ? acc[i][j][e2 * 2 + 0] * scale : 0.f;
                float v1 = (w0 + 1 >= 0 && w0 + 1 <= 32) ? acc[i][j][e2 * 2 + 1] * scale : 0.f;
                float2 v; v.x = v0; v.y = v1;
                *(float2*)&Sw[m * SS + c0] = v;
            }
        }
    }
    __syncwarp();

    // ---- softmax per query (lane = local query m) ----
    float* Pc = Qs + wid * 32 * QS;          // dead Qs region; stride 33 scatter
    {
        const int m = lane;
        float* row = Sw + m * SS;
        float sc[33];
#pragma unroll
        for (int w = 0; w < 33; w++) sc[w] = row[m + w];
        float mx = sc[0];
#pragma unroll
        for (int w = 1; w < 33; w++) mx = fmaxf(mx, sc[w]);
        float ssum = 0.f;
#pragma unroll
        for (int w = 0; w < 33; w++) { sc[w] = __expf(sc[w] - mx); ssum += sc[w]; }
        const float rinv = 1.f / ssum;
#pragma unroll
        for (int w = 0; w < 33; w++) {
            float p = sc[w] * rinv;
            Pc[m * 33 + w] = p;
            row[m + w] = __uint_as_float(f2tf32(p));
        }
    }
    __syncwarp();

    // Warp-coalesced probs store: 32 queries x 33 floats contiguous in gmem.
    {
        float* gp = probs_out + ((size_t)bh * Nc + n0 + wid * 32) * Wc;
        const float4* Ps4 = (const float4*)Pc;
        float4* Gp4 = (float4*)gp;
#pragma unroll
        for (int i = lane; i < 264; i += 32)   // 1056 floats = 264 float4
            Gp4[i] = Ps4[i];
    }

    // ---- ctx = P(32x64) @ V(64x32) via tf32 MMA ----
    // Row block i uses P cols [i*16, i*16+47] -> i=0: kk8 in [0,5]; i=1: [2,7].
    float acc2[2][4][4];
#pragma unroll
    for (int i = 0; i < 2; i++)
#pragma unroll
        for (int j = 0; j < 4; j++)
#pragma unroll
            for (int e = 0; e < 4; e++) acc2[i][j][e] = 0.f;

#pragma unroll
    for (int kk8 = 0; kk8 < 8; kk8++) {
        const int kk = kk8 * 8;
        uint32_t bf[4][2];
#pragma unroll
        for (int j = 0; j < 4; j++) {
            int nb = (j * 8 + gr) * VS + woff + kk + gc;
            bf[j][0] = __float_as_uint(Vt[nb]);
            bf[j][1] = __float_as_uint(Vt[nb + 4]);
        }
#pragma unroll
        for (int i = 0; i < 2; i++) {
            if (i == 0 && kk8 >= 6) continue;   // P cols 48+ zero for rows 0..15
            if (i == 1 && kk8 <= 1) continue;   // P cols <16 zero for rows 16..31
            uint32_t af[4];
            int rb = (i * 16 + gr) * SS + kk + gc;
            af[0] = __float_as_uint(Sw[rb]);
            af[1] = __float_as_uint(Sw[rb + 8 * SS]);
            af[2] = __float_as_uint(Sw[rb + 4]);
            af[3] = __float_as_uint(Sw[rb + 8 * SS + 4]);
#pragma unroll
            for (int j = 0; j < 4; j++)
                mma_tf32(acc2[i][j][0], acc2[i][j][1], acc2[i][j][2], acc2[i][j][3],
                         af[0], af[1], af[2], af[3], bf[j][0], bf[j][1]);
        }
    }

    // Epilogue: ctx -> (B,N,E)
    const int b = bh >> 2;
    const int h = bh & 3;
#pragma unroll
    for (int i = 0; i < 2; i++) {
#pragma unroll
        for (int j = 0; j < 4; j++) {
            int d = j * 8 + gc * 2;
#pragma unroll
            for (int e2 = 0; e2 < 2; e2++) {
                int m = i * 16 + gr + e2 * 8;
                float2 v;
                v.x = acc2[i][j][e2 * 2 + 0];
                v.y = acc2[i][j][e2 * 2 + 1];
                *(float2*)(g_ctx + ((size_t)(b * Nc) + n0 + wid * 32 + m) * Ec + h * 32 + d) = v;
            }
        }
    }
}

// ---------------------------------------------------------------------------
extern "C" void kernel_launch(void* const* d_in, const int* in_sizes, int n_in,
                              void* d_out, int out_size)
{
    (void)in_sizes; (void)n_in; (void)out_size;
    const float* q  = (const float*)d_in[0];
    const float* Wq = (const float*)d_in[1];
    const float* bq = (const float*)d_in[2];
    const float* Wk = (const float*)d_in[3];
    const float* bk = (const float*)d_in[4];
    const float* Wv = (const float*)d_in[5];
    const float* bv = (const float*)d_in[6];
    const float* Wo = (const float*)d_in[7];
    const float* bo = (const float*)d_in[8];

    float* outp  = (float*)d_out;                         // (B,N,E)
    float* probs = outp + (size_t)Bc * Nc * Ec;           // (B,H,N,W)

    const int attn_smem = (128 * QS + 160 * QS + 32 * VS + 4 * 32 * SS) * 4; // 97408 B
    cudaFuncSetAttribute(attn_mma, cudaFuncAttributeMaxDynamicSharedMemorySize, attn_smem);

    qkv_mma<<<dim3(Mc / 128, 3), 256>>>(q, Wq, bq, Wk, bk, Wv, bv);
    attn_mma<<<dim3(Nc / 128, BHc), 128, attn_smem>>>(probs);
    out_mma<<<dim3(Mc / 128, 1), 256>>>(Wo, bo, outp);
}

// round 8
// speedup vs baseline: 1.2471x; 1.0171x over previous
#include <cuda_runtime.h>
#include <math.h>
#include <stdint.h>

// Problem constants
#define Bc 4
#define Nc 8192
#define Ec 128
#define Hc 4
#define Dc 32
#define PADc 16
#define Wc 33
#define BHc 16
#define Mc (Bc * Nc)   // 32768 rows

// Scratch (device globals: no allocation allowed in kernel_launch)
__device__ float g_Q[(size_t)BHc * Nc * Dc];     // (B,H,N,D)
__device__ float g_K[(size_t)BHc * Nc * Dc];
__device__ float g_V[(size_t)BHc * Nc * Dc];
__device__ float g_ctx[(size_t)Mc * Ec];          // (B,N,E)

__device__ __forceinline__ uint32_t f2tf32(float x) {
    uint32_t r;
    asm("cvt.rna.tf32.f32 %0, %1;" : "=r"(r) : "f"(x));
    return r;
}

__device__ __forceinline__ uint32_t hi_bits(float x) {
    return __float_as_uint(x) & 0xFFFFE000u;
}

__device__ __forceinline__ void mma_tf32(
    float& c0, float& c1, float& c2, float& c3,
    uint32_t a0, uint32_t a1, uint32_t a2, uint32_t a3,
    uint32_t b0, uint32_t b1)
{
    asm volatile(
        "mma.sync.aligned.m16n8k8.row.col.f32.tf32.tf32.f32 "
        "{%0,%1,%2,%3}, {%4,%5,%6,%7}, {%8,%9}, {%0,%1,%2,%3};\n"
        : "+f"(c0), "+f"(c1), "+f"(c2), "+f"(c3)
        : "r"(a0), "r"(a1), "r"(a2), "r"(a3), "r"(b0), "r"(b1));
}

// ldmatrix x4: four 8x8 b16 matrices (= four 8x4 tf32 tiles).
// With stride-36-float rows: 8 rows x 4 banks -> all 32 banks, conflict-free.
__device__ __forceinline__ void ldsm_x4(
    uint32_t& r0, uint32_t& r1, uint32_t& r2, uint32_t& r3, uint32_t saddr)
{
    asm volatile("ldmatrix.sync.aligned.m8n8.x4.shared.b16 {%0,%1,%2,%3}, [%4];"
                 : "=r"(r0), "=r"(r1), "=r"(r2), "=r"(r3) : "r"(saddr));
}

// ---------------------------------------------------------------------------
// tf32 MMA GEMM core (R3 layout + LDSM fragment loads):
// C(128x128) = A(128x128) @ B(128x128)^T  (+bias)
// 256 threads = 8 warps; warp grid 4(M) x 2(N); warp tile 32x64.
// smem stride 36; cvt to tf32 at staging time; ldmatrix.x4 fragment loads
// (2 LDSM for A + 4 LDSM for B per kk-step, replacing 24 LDS.32).
// ---------------------------------------------------------------------------
#define GEMM_MMA_BODY(A_PTR, B_PTR, EPILOGUE)                                   \
    __shared__ uint32_t As[128 * 36];                                           \
    __shared__ uint32_t Bs[128 * 36];                                           \
    const int tid  = threadIdx.x;                                               \
    const int wid  = tid >> 5;                                                  \
    const int lane = tid & 31;                                                  \
    const int wm   = wid >> 1;       /* 0..3 */                                 \
    const int wn   = wid & 1;        /* 0..1 */                                 \
    const int gr   = lane >> 2;      /* 0..7 */                                 \
    const int gc   = lane & 3;       /* 0..3 */                                 \
    const int lm   = lane >> 3;      /* ldmatrix matrix idx 0..3 */             \
    const int lr   = lane & 7;       /* ldmatrix row-in-matrix */               \
    const int m0   = blockIdx.x * 128;                                          \
    const uint32_t asB = (uint32_t)__cvta_generic_to_shared(As);                \
    const uint32_t bsB = (uint32_t)__cvta_generic_to_shared(Bs);                \
    uint32_t aAddr[2], bAddr[4];                                                \
    _Pragma("unroll")                                                           \
    for (int i = 0; i < 2; i++)                                                 \
        aAddr[i] = asB + (((wm * 32 + i * 16 + (lm & 1) * 8 + lr) * 36          \
                           + (lm >> 1) * 4) << 2);                              \
    _Pragma("unroll")                                                           \
    for (int j2 = 0; j2 < 4; j2++)                                              \
        bAddr[j2] = bsB + (((wn * 64 + j2 * 16 + (lm >> 1) * 8 + lr) * 36       \
                            + (lm & 1) * 4) << 2);                              \
    float acc[2][8][4];                                                         \
    _Pragma("unroll")                                                           \
    for (int i = 0; i < 2; i++)                                                 \
        _Pragma("unroll")                                                       \
        for (int j = 0; j < 8; j++)                                             \
            _Pragma("unroll")                                                   \
            for (int e = 0; e < 4; e++) acc[i][j][e] = 0.f;                     \
    for (int k0 = 0; k0 < 128; k0 += 32) {                                      \
        _Pragma("unroll")                                                       \
        for (int l = 0; l < 4; l++) {                                           \
            int li = tid + l * 256;                                             \
            int r  = li >> 3;                                                   \
            int c4 = (li & 7) * 4;                                              \
            float4 va = *(const float4*)(A_PTR + (size_t)(m0 + r) * 128 + k0 + c4); \
            As[r * 36 + c4 + 0] = f2tf32(va.x);                                 \
            As[r * 36 + c4 + 1] = f2tf32(va.y);                                 \
            As[r * 36 + c4 + 2] = f2tf32(va.z);                                 \
            As[r * 36 + c4 + 3] = f2tf32(va.w);                                 \
            float4 vb = *(const float4*)(B_PTR + (size_t)r * 128 + k0 + c4);    \
            Bs[r * 36 + c4 + 0] = f2tf32(vb.x);                                 \
            Bs[r * 36 + c4 + 1] = f2tf32(vb.y);                                 \
            Bs[r * 36 + c4 + 2] = f2tf32(vb.z);                                 \
            Bs[r * 36 + c4 + 3] = f2tf32(vb.w);                                 \
        }                                                                       \
        __syncthreads();                                                        \
        _Pragma("unroll")                                                       \
        for (int kk = 0; kk < 32; kk += 8) {                                    \
            uint32_t af[2][4];                                                  \
            _Pragma("unroll")                                                   \
            for (int i = 0; i < 2; i++)                                         \
                ldsm_x4(af[i][0], af[i][1], af[i][2], af[i][3],                 \
                        aAddr[i] + kk * 4);                                     \
            uint32_t bf[8][2];                                                  \
            _Pragma("unroll")                                                   \
            for (int j2 = 0; j2 < 4; j2++)                                      \
                ldsm_x4(bf[2 * j2][0], bf[2 * j2][1],                           \
                        bf[2 * j2 + 1][0], bf[2 * j2 + 1][1],                   \
                        bAddr[j2] + kk * 4);                                    \
            _Pragma("unroll")                                                   \
            for (int i = 0; i < 2; i++)                                         \
                _Pragma("unroll")                                               \
                for (int j = 0; j < 8; j++)                                     \
                    mma_tf32(acc[i][j][0], acc[i][j][1], acc[i][j][2], acc[i][j][3], \
                             af[i][0], af[i][1], af[i][2], af[i][3],            \
                             bf[j][0], bf[j][1]);                               \
        }                                                                       \
        __syncthreads();                                                        \
    }                                                                           \
    EPILOGUE

// ---------------------------------------------------------------------------
// Kernel 1: fused QKV projection -> (B,H,N,D) scatter.  grid = (256, 3)
// ---------------------------------------------------------------------------
__global__ __launch_bounds__(256, 2) void qkv_mma(
    const float* __restrict__ q,
    const float* __restrict__ Wq, const float* __restrict__ bq,
    const float* __restrict__ Wk, const float* __restrict__ bk,
    const float* __restrict__ Wv, const float* __restrict__ bv)
{
    const int which = blockIdx.y;
    const float* __restrict__ Wm = (which == 0) ? Wq : ((which == 1) ? Wk : Wv);
    const float* __restrict__ bm = (which == 0) ? bq : ((which == 1) ? bk : bv);
    float* __restrict__ outp = (which == 0) ? g_Q : ((which == 1) ? g_K : g_V);

    GEMM_MMA_BODY(q, Wm,
    {
        _Pragma("unroll")
        for (int i = 0; i < 2; i++) {
            _Pragma("unroll")
            for (int e2 = 0; e2 < 2; e2++) {
                int m = m0 + wm * 32 + i * 16 + gr + e2 * 8;
                int b = m >> 13;
                int n = m & 8191;
                _Pragma("unroll")
                for (int j = 0; j < 8; j++) {
                    int col = wn * 64 + j * 8 + gc * 2;
                    int h = col >> 5;
                    int d = col & 31;
                    float2 v;
                    v.x = acc[i][j][e2 * 2 + 0] + bm[col];
                    v.y = acc[i][j][e2 * 2 + 1] + bm[col + 1];
                    *(float2*)(outp + ((size_t)(b * Hc + h) * Nc + n) * Dc + d) = v;
                }
            }
        }
    })
}

// ---------------------------------------------------------------------------
// Kernel 3: output projection. out = ctx @ Wo.T + bo -> d_out (B,N,E)
// ---------------------------------------------------------------------------
__global__ __launch_bounds__(256, 2) void out_mma(
    const float* __restrict__ Wo, const float* __restrict__ bo,
    float* __restrict__ outp)
{
    const float* __restrict__ ctxp = g_ctx;
    GEMM_MMA_BODY(ctxp, Wo,
    {
        _Pragma("unroll")
        for (int i = 0; i < 2; i++) {
            _Pragma("unroll")
            for (int e2 = 0; e2 < 2; e2++) {
                int m = m0 + wm * 32 + i * 16 + gr + e2 * 8;
                _Pragma("unroll")
                for (int j = 0; j < 8; j++) {
                    int col = wn * 64 + j * 8 + gc * 2;
                    float2 v;
                    v.x = acc[i][j][e2 * 2 + 0] + bo[col];
                    v.y = acc[i][j][e2 * 2 + 1] + bo[col + 1];
                    *(float2*)(outp + (size_t)m * 128 + col) = v;
                }
            }
        }
    })
}

// ---------------------------------------------------------------------------
// Kernel 2: warp-independent tensorized sliding-window attention.
// Block = 128 queries (4 warps x 32 queries); each warp owns a dense
// 64-key window of its 32-query band. S = Q@Kwin^T via split-tf32 (exact
// scores); OOB keys zero-padded (score exactly 0, matching reference);
// out-of-band entries zeroed. Band-zero MMAs skipped. QK fragments loaded
// via ldmatrix (raw fp32 bits), hi/lo split in regs. Probs staged
// compactly in smem then stored warp-coalesced.
// grid = (N/128, BH), 128 threads.
// ---------------------------------------------------------------------------
#define QS 36     // Qs/Ks stride
#define VS 165    // Vt stride: 165 mod 32 = 5 -> conflict-free stores & loads
#define SS 68     // per-warp S stride: 68 mod 32 = 4

__global__ __launch_bounds__(128) void attn_mma(float* __restrict__ probs_out)
{
    extern __shared__ float sm[];
    float* Qs   = sm;                       // 128 x 36 raw fp32 (reused for probs)
    float* Ks   = Qs + 128 * QS;            // 160 x 36 raw fp32 (zero OOB)
    float* Vt   = Ks + 160 * QS;            // 32 x 165 tf32 transposed (zero OOB)
    float* Sall = Vt + 32 * VS;             // 4 warps x (32 x 68)

    const int tile = blockIdx.x;            // 0..63
    const int bh   = blockIdx.y;            // 0..15
    const int tid  = threadIdx.x;
    const int wid  = tid >> 5;              // 0..3
    const int lane = tid & 31;
    const int gr   = lane >> 2;
    const int gc   = lane & 3;
    const int lm   = lane >> 3;
    const int lr   = lane & 7;
    const int n0   = tile * 128;
    const int g0   = n0 - PADc;

    const float* __restrict__ Qg = g_Q + (size_t)bh * Nc * Dc;
    const float* __restrict__ Kg = g_K + (size_t)bh * Nc * Dc;
    const float* __restrict__ Vg = g_V + (size_t)bh * Nc * Dc;

    // Stage Q (128x32)
#pragma unroll
    for (int l = 0; l < 8; l++) {
        int idx = tid + l * 128;            // 0..1023
        int r   = idx >> 3;
        int c4  = (idx & 7) * 4;
        *(float4*)&Qs[r * QS + c4] = *(const float4*)(Qg + (size_t)(n0 + r) * 32 + c4);
    }
    // Stage K (160x32 raw, zero OOB) and V transposed (tf32, zero OOB)
#pragma unroll
    for (int l = 0; l < 10; l++) {
        int idx = tid + l * 128;            // 0..1279
        int r   = idx >> 3;                 // 0..159
        int c4  = (idx & 7) * 4;
        int grow = g0 + r;
        float4 kv = make_float4(0.f, 0.f, 0.f, 0.f);
        float4 vv = make_float4(0.f, 0.f, 0.f, 0.f);
        if (grow >= 0 && grow < Nc) {
            kv = *(const float4*)(Kg + (size_t)grow * 32 + c4);
            vv = *(const float4*)(Vg + (size_t)grow * 32 + c4);
        }
        *(float4*)&Ks[r * QS + c4] = kv;
        Vt[(c4 + 0) * VS + r] = __uint_as_float(f2tf32(vv.x));
        Vt[(c4 + 1) * VS + r] = __uint_as_float(f2tf32(vv.y));
        Vt[(c4 + 2) * VS + r] = __uint_as_float(f2tf32(vv.z));
        Vt[(c4 + 3) * VS + r] = __uint_as_float(f2tf32(vv.w));
    }
    __syncthreads();

    float* Sw = Sall + wid * (32 * SS);
    const int woff = wid * 32;              // warp's key-window offset in staged rows

    // ldmatrix addresses for QK fragments (raw fp32 bits)
    const uint32_t qsB = (uint32_t)__cvta_generic_to_shared(Qs);
    const uint32_t ksB = (uint32_t)__cvta_generic_to_shared(Ks);
    uint32_t qAddr[2], kAddr[4];
#pragma unroll
    for (int i = 0; i < 2; i++)
        qAddr[i] = qsB + (((woff + i * 16 + (lm & 1) * 8 + lr) * QS + (lm >> 1) * 4) << 2);
#pragma unroll
    for (int j2 = 0; j2 < 4; j2++)
        kAddr[j2] = ksB + (((woff + j2 * 16 + (lm >> 1) * 8 + lr) * QS + (lm & 1) * 4) << 2);

    // ---- QK^T: S(32x64) via split-tf32 (hh + hl + lh) ----
    // Band: row m uses cols [m, m+32]. Fragment block (i,j): i=0: j in [0,5];
    // i=1: j in [2,7]. Others provably zero.
    float acc[2][8][4];
#pragma unroll
    for (int i = 0; i < 2; i++)
#pragma unroll
        for (int j = 0; j < 8; j++)
#pragma unroll
            for (int e = 0; e < 4; e++) acc[i][j][e] = 0.f;

#pragma unroll
    for (int kk = 0; kk < 32; kk += 8) {
        uint32_t ah[2][4], al[2][4];
#pragma unroll
        for (int i = 0; i < 2; i++) {
            uint32_t raw[4];
            ldsm_x4(raw[0], raw[1], raw[2], raw[3], qAddr[i] + kk * 4);
#pragma unroll
            for (int e = 0; e < 4; e++) {
                float x = __uint_as_float(raw[e]);
                ah[i][e] = raw[e] & 0xFFFFE000u;
                al[i][e] = __float_as_uint(x - __uint_as_float(ah[i][e]));
            }
        }
        uint32_t bhf[8][2], blf[8][2];
#pragma unroll
        for (int j2 = 0; j2 < 4; j2++) {
            uint32_t raw[4];
            ldsm_x4(raw[0], raw[1], raw[2], raw[3], kAddr[j2] + kk * 4);
#pragma unroll
            for (int e = 0; e < 4; e++) {
                int j = 2 * j2 + (e >> 1);
                int s = e & 1;
                float y = __uint_as_float(raw[e]);
                bhf[j][s] = raw[e] & 0xFFFFE000u;
                blf[j][s] = __float_as_uint(y - __uint_as_float(bhf[j][s]));
            }
        }
#pragma unroll
        for (int i = 0; i < 2; i++)
#pragma unroll
            for (int j = 0; j < 8; j++) {
                if (i == 0 && j >= 6) continue;   // fully out-of-band
                if (i == 1 && j <= 1) continue;   // fully out-of-band
                mma_tf32(acc[i][j][0], acc[i][j][1], acc[i][j][2], acc[i][j][3],
                         al[i][0], al[i][1], al[i][2], al[i][3], bhf[j][0], bhf[j][1]);
                mma_tf32(acc[i][j][0], acc[i][j][1], acc[i][j][2], acc[i][j][3],
                         ah[i][0], ah[i][1], ah[i][2], ah[i][3], blf[j][0], blf[j][1]);
                mma_tf32(acc[i][j][0], acc[i][j][1], acc[i][j][2], acc[i][j][3],
                         ah[i][0], ah[i][1], ah[i][2], ah[i][3], bhf[j][0], bhf[j][1]);
            }
    }

    // Epilogue: scale in-band (0 <= c-m <= 32), zero out-of-band
    const float scale = 0.17677669529663687f;   // 1/sqrt(32)
#pragma unroll
    for (int i = 0; i < 2; i++) {
#pragma unroll
        for (int j = 0; j < 8; j++) {
            int c0 = j * 8 + gc * 2;
#pragma unroll
            for (int e2 = 0; e2 < 2; e2++) {
                int m = i * 16 + gr + e2 * 8;
                int w0 = c0 - m;
                float v0 = (w0 >= 0     && w0 <= 32) ? acc[i][j][e2 * 2 + 0] * scale : 0.f;
                float v1 = (w0 + 1 >= 0 && w0 + 1 <= 32) ? acc[i][j][e2 * 2 + 1] * scale : 0.f;
                float2 v; v.x = v0; v.y = v1;
                *(float2*)&Sw[m * SS + c0] = v;
            }
        }
    }
    __syncwarp();

    // ---- softmax per query (lane = local query m) ----
    float* Pc = Qs + wid * 32 * QS;          // dead Qs region; stride 33 scatter
    {
        const int m = lane;
        float* row = Sw + m * SS;
        float sc[33];
#pragma unroll
        for (int w = 0; w < 33; w++) sc[w] = row[m + w];
        float mx = sc[0];
#pragma unroll
        for (int w = 1; w < 33; w++) mx = fmaxf(mx, sc[w]);
        float ssum = 0.f;
#pragma unroll
        for (int w = 0; w < 33; w++) { sc[w] = __expf(sc[w] - mx); ssum += sc[w]; }
        const float rinv = 1.f / ssum;
#pragma unroll
        for (int w = 0; w < 33; w++) {
            float p = sc[w] * rinv;
            Pc[m * 33 + w] = p;
            row[m + w] = __uint_as_float(f2tf32(p));
        }
    }
    __syncwarp();

    // Warp-coalesced probs store: 32 queries x 33 floats contiguous in gmem.
    {
        float* gp = probs_out + ((size_t)bh * Nc + n0 + wid * 32) * Wc;
        const float4* Ps4 = (const float4*)Pc;
        float4* Gp4 = (float4*)gp;
#pragma unroll
        for (int i = lane; i < 264; i += 32)   // 1056 floats = 264 float4
            Gp4[i] = Ps4[i];
    }

    // ---- ctx = P(32x64) @ V(64x32) via tf32 MMA ----
    // Row block i uses P cols [i*16, i*16+47] -> i=0: kk8 in [0,5]; i=1: [2,7].
    float acc2[2][4][4];
#pragma unroll
    for (int i = 0; i < 2; i++)
#pragma unroll
        for (int j = 0; j < 4; j++)
#pragma unroll
            for (int e = 0; e < 4; e++) acc2[i][j][e] = 0.f;

#pragma unroll
    for (int kk8 = 0; kk8 < 8; kk8++) {
        const int kk = kk8 * 8;
        uint32_t bf[4][2];
#pragma unroll
        for (int j = 0; j < 4; j++) {
            int nb = (j * 8 + gr) * VS + woff + kk + gc;
            bf[j][0] = __float_as_uint(Vt[nb]);
            bf[j][1] = __float_as_uint(Vt[nb + 4]);
        }
#pragma unroll
        for (int i = 0; i < 2; i++) {
            if (i == 0 && kk8 >= 6) continue;   // P cols 48+ zero for rows 0..15
            if (i == 1 && kk8 <= 1) continue;   // P cols <16 zero for rows 16..31
            uint32_t af[4];
            int rb = (i * 16 + gr) * SS + kk + gc;
            af[0] = __float_as_uint(Sw[rb]);
            af[1] = __float_as_uint(Sw[rb + 8 * SS]);
            af[2] = __float_as_uint(Sw[rb + 4]);
            af[3] = __float_as_uint(Sw[rb + 8 * SS + 4]);
#pragma unroll
            for (int j = 0; j < 4; j++)
                mma_tf32(acc2[i][j][0], acc2[i][j][1], acc2[i][j][2], acc2[i][j][3],
                         af[0], af[1], af[2], af[3], bf[j][0], bf[j][1]);
        }
    }

    // Epilogue: ctx -> (B,N,E)
    const int b = bh >> 2;
    const int h = bh & 3;
#pragma unroll
    for (int i = 0; i < 2; i++) {
#pragma unroll
        for (int j = 0; j < 4; j++) {
            int d = j * 8 + gc * 2;
#pragma unroll
            for (int e2 = 0; e2 < 2; e2++) {
                int m = i * 16 + gr + e2 * 8;
                float2 v;
                v.x = acc2[i][j][e2 * 2 + 0];
                v.y = acc2[i][j][e2 * 2 + 1];
                *(float2*)(g_ctx + ((size_t)(b * Nc) + n0 + wid * 32 + m) * Ec + h * 32 + d) = v;
            }
        }
    }
}

// ---------------------------------------------------------------------------
extern "C" void kernel_launch(void* const* d_in, const int* in_sizes, int n_in,
                              void* d_out, int out_size)
{
    (void)in_sizes; (void)n_in; (void)out_size;
    const float* q  = (const float*)d_in[0];
    const float* Wq = (const float*)d_in[1];
    const float* bq = (const float*)d_in[2];
    const float* Wk = (const float*)d_in[3];
    const float* bk = (const float*)d_in[4];
    const float* Wv = (const float*)d_in[5];
    const float* bv = (const float*)d_in[6];
    const float* Wo = (const float*)d_in[7];
    const float* bo = (const float*)d_in[8];

    float* outp  = (float*)d_out;                         // (B,N,E)
    float* probs = outp + (size_t)Bc * Nc * Ec;           // (B,H,N,W)

    const int attn_smem = (128 * QS + 160 * QS + 32 * VS + 4 * 32 * SS) * 4; // 97408 B
    cudaFuncSetAttribute(attn_mma, cudaFuncAttributeMaxDynamicSharedMemorySize, attn_smem);

    qkv_mma<<<dim3(Mc / 128, 3), 256>>>(q, Wq, bq, Wk, bk, Wv, bv);
    attn_mma<<<dim3(Nc / 128, BHc), 128, attn_smem>>>(probs);
    out_mma<<<dim3(Mc / 128, 1), 256>>>(Wo, bo, outp);
}